// round 14
// baseline (speedup 1.0000x reference)
#include <cuda_runtime.h>
#include <cuda_fp16.h>
#include <cstdint>

#define N_NODES 50000
#define N_EDGES 800000
#define CSR_STRIDE 64          /* max in-degree+1; Poisson(16) -> overflow P ~1e-22 */
#define NEG_SLOPE 0.2f
#define FRONT_BLOCKS 304
#define SCAT_BLOCKS 128
#define NTILES1 782            /* ceil(50000/64) */
#define GEMM_TILES_MAIN 704    /* 176 gemm blocks x 4 tiles; 78-tile tail on scatter blocks */

// ---------------- scratch (static device globals; no runtime alloc) ----------------
__device__ __half g_h1[N_NODES * 128];     // x @ W1 (fp16, gather source)
__device__ __half g_hrelu[N_NODES * 128];  // relu(gat1) (fp16, GEMM2 A)
__device__ __half g_h2[N_NODES * 64];      // hrelu @ W2 (fp16, gather source)
__device__ __half g_W1h[128 * 128];        // W1 fp16, [n][k]
__device__ __half g_W2h[64 * 128];         // W2 fp16, [n][k]
__device__ float  g_als1[N_NODES * 4];
__device__ float  g_ald1[N_NODES * 4];
__device__ float  g_als2[N_NODES];
__device__ float  g_ald2[N_NODES];
__device__ int    g_cursor[N_NODES];
__device__ int    g_csr[N_NODES * CSR_STRIDE];

__device__ __forceinline__ float lrelu(float e) {
    return e >= 0.f ? e : NEG_SLOPE * e;
}

__device__ __forceinline__ uint32_t smem_u32(const void* p) {
    return (uint32_t)__cvta_generic_to_shared(p);
}

__device__ __forceinline__ void ldsm4(uint32_t& r0, uint32_t& r1, uint32_t& r2,
                                      uint32_t& r3, uint32_t addr) {
    asm volatile("ldmatrix.sync.aligned.m8n8.x4.shared.b16 {%0,%1,%2,%3}, [%4];"
                 : "=r"(r0), "=r"(r1), "=r"(r2), "=r"(r3) : "r"(addr));
}

__device__ __forceinline__ void mma16816(float* d, const uint32_t* a, const uint32_t* b) {
    asm volatile(
        "mma.sync.aligned.m16n8k16.row.col.f32.f16.f16.f32 "
        "{%0,%1,%2,%3}, {%4,%5,%6,%7}, {%8,%9}, {%0,%1,%2,%3};"
        : "+f"(d[0]), "+f"(d[1]), "+f"(d[2]), "+f"(d[3])
        : "r"(a[0]), "r"(a[1]), "r"(a[2]), "r"(a[3]), "r"(b[0]), "r"(b[1]));
}

__device__ __forceinline__ void cp16(uint32_t dst, const void* src) {
    asm volatile("cp.async.cg.shared.global [%0], [%1], 16;" :: "r"(dst), "l"(src));
}

// ------- init: cursors + self-loops + one-time W1/W2 fp16 transposed copies -------
__global__ void k_init(const float* __restrict__ W1, const float* __restrict__ W2) {
    int i = blockIdx.x * blockDim.x + threadIdx.x;
    if (i < N_NODES) {
        g_csr[i * CSR_STRIDE] = i;          // appended self-loop in slot 0
        g_cursor[i] = i * CSR_STRIDE + 1;
    }
    if (i < 128 * 128) {
        int k = i >> 7, n = i & 127;
        g_W1h[n * 128 + k] = __float2half_rn(W1[k * 128 + n]);
    }
    if (i < 64 * 128) {
        int k = i >> 6, n = i & 63;
        g_W2h[n * 128 + k] = __float2half_rn(W2[k * 64 + n]);
    }
}

// ---- fused front: unrolled edge scatter (blocks 0..127) + HMMA GEMM1 + logits1 ----
__global__ __launch_bounds__(256)
void k_front(const float* __restrict__ A,
             __half* __restrict__ C,
             const float* __restrict__ a_s, const float* __restrict__ a_d,
             float* __restrict__ als, float* __restrict__ ald,
             const int* __restrict__ src, const int* __restrict__ dst) {
    extern __shared__ uint4 sm[];        // [0,1024): A 64x16; [1024,3072): W 128x16
    uint4* Asw = sm;
    uint4* Wsw = sm + 1024;

    int tid = threadIdx.x;
    int bid = blockIdx.x;

    int t0, t1;
    if (bid < SCAT_BLOCKS) {
        // ---- scatter, 8-way unrolled for atomic MLP ----
        constexpr int STRIDE = SCAT_BLOCKS * 256;     // 32768
        int e = bid * 256 + tid;
        for (; e + 7 * STRIDE < N_EDGES; e += 8 * STRIDE) {
            int s[8], d[8], p[8];
            #pragma unroll
            for (int u = 0; u < 8; u++) {
                s[u] = src[e + u * STRIDE];
                d[u] = dst[e + u * STRIDE];
            }
            #pragma unroll
            for (int u = 0; u < 8; u++)
                p[u] = (s[u] != d[u]) ? atomicAdd(&g_cursor[d[u]], 1) : -1;
            #pragma unroll
            for (int u = 0; u < 8; u++)
                if (p[u] >= 0) g_csr[p[u]] = s[u];
        }
        for (; e < N_EDGES; e += STRIDE) {
            int s = src[e], d = dst[e];
            if (s != d) {
                int p = atomicAdd(&g_cursor[d], 1);
                g_csr[p] = s;
            }
        }
        t0 = GEMM_TILES_MAIN + bid;
        t1 = (bid < NTILES1 - GEMM_TILES_MAIN) ? t0 + 1 : t0;
    } else {
        int nb = bid - SCAT_BLOCKS;
        t0 = nb * 4; t1 = t0 + 4;
    }
    if (t0 >= t1) return;

    for (int u = tid; u < 2048; u += 256) {
        int n = u >> 4, kc = u & 15;
        Wsw[n * 16 + (kc ^ (n & 7))] = *(const uint4*)&g_W1h[n * 128 + kc * 8];
    }

    int lane = tid & 31, wid = tid >> 5;
    int wm = wid >> 2, wn = wid & 3;
    int grp = lane >> 2, qid = lane & 3;

    float asr[4][2], adr[4][2];
    #pragma unroll
    for (int nj = 0; nj < 4; nj++) {
        int col = wn * 32 + nj * 8 + qid * 2;
        asr[nj][0] = a_s[col]; asr[nj][1] = a_s[col + 1];
        adr[nj][0] = a_d[col]; adr[nj][1] = a_d[col + 1];
    }

    uint32_t aBase = smem_u32(Asw);
    uint32_t wBase = smem_u32(Wsw);
    int aRowL = (lane & 7) + ((lane >> 3) & 1) * 8;
    int aChkL = lane >> 4;
    int bRowL = (lane & 7) + (lane >> 4) * 8;
    int bChkL = (lane >> 3) & 1;

    for (int tile = t0; tile < t1; tile++) {
        int rowBase = tile * 64;
        __syncthreads();
        for (int u = tid; u < 1024; u += 256) {
            int r = u >> 4, c = u & 15;
            int row = rowBase + r;
            uint4 val = make_uint4(0u, 0u, 0u, 0u);
            if (row < N_NODES) {
                float4 f0 = *(const float4*)&A[row * 128 + c * 8];
                float4 f1 = *(const float4*)&A[row * 128 + c * 8 + 4];
                __align__(16) __half h8[8];
                h8[0] = __float2half_rn(f0.x); h8[1] = __float2half_rn(f0.y);
                h8[2] = __float2half_rn(f0.z); h8[3] = __float2half_rn(f0.w);
                h8[4] = __float2half_rn(f1.x); h8[5] = __float2half_rn(f1.y);
                h8[6] = __float2half_rn(f1.z); h8[7] = __float2half_rn(f1.w);
                val = *(const uint4*)h8;
            }
            Asw[r * 16 + (c ^ (r & 7))] = val;
        }
        __syncthreads();

        float acc[2][4][4];
        #pragma unroll
        for (int mi = 0; mi < 2; mi++)
            #pragma unroll
            for (int nj = 0; nj < 4; nj++)
                #pragma unroll
                for (int q = 0; q < 4; q++) acc[mi][nj][q] = 0.f;

        #pragma unroll
        for (int ks = 0; ks < 8; ks++) {
            uint32_t aF[2][4], bF[2][4];
            #pragma unroll
            for (int mi = 0; mi < 2; mi++) {
                int row = wm * 32 + mi * 16 + aRowL;
                int ch = ks * 2 + aChkL;
                ldsm4(aF[mi][0], aF[mi][1], aF[mi][2], aF[mi][3],
                      aBase + (uint32_t)(row * 16 + (ch ^ (row & 7))) * 16u);
            }
            #pragma unroll
            for (int pr = 0; pr < 2; pr++) {
                int n = wn * 32 + pr * 16 + bRowL;
                int ch = ks * 2 + bChkL;
                ldsm4(bF[pr][0], bF[pr][1], bF[pr][2], bF[pr][3],
                      wBase + (uint32_t)(n * 16 + (ch ^ (n & 7))) * 16u);
            }
            #pragma unroll
            for (int mi = 0; mi < 2; mi++)
                #pragma unroll
                for (int nj = 0; nj < 4; nj++)
                    mma16816(acc[mi][nj], aF[mi], &bF[nj >> 1][(nj & 1) * 2]);
        }

        #pragma unroll
        for (int mi = 0; mi < 2; mi++) {
            int rLo = rowBase + wm * 32 + mi * 16 + grp;
            int rHi = rLo + 8;
            float psLo = 0.f, pdLo = 0.f, psHi = 0.f, pdHi = 0.f;
            #pragma unroll
            for (int nj = 0; nj < 4; nj++) {
                psLo += acc[mi][nj][0] * asr[nj][0] + acc[mi][nj][1] * asr[nj][1];
                pdLo += acc[mi][nj][0] * adr[nj][0] + acc[mi][nj][1] * adr[nj][1];
                psHi += acc[mi][nj][2] * asr[nj][0] + acc[mi][nj][3] * asr[nj][1];
                pdHi += acc[mi][nj][2] * adr[nj][0] + acc[mi][nj][3] * adr[nj][1];
                int col = wn * 32 + nj * 8 + qid * 2;
                if (rLo < N_NODES)
                    *(__half2*)&C[rLo * 128 + col] =
                        __floats2half2_rn(acc[mi][nj][0], acc[mi][nj][1]);
                if (rHi < N_NODES)
                    *(__half2*)&C[rHi * 128 + col] =
                        __floats2half2_rn(acc[mi][nj][2], acc[mi][nj][3]);
            }
            psLo += __shfl_xor_sync(~0u, psLo, 1); psLo += __shfl_xor_sync(~0u, psLo, 2);
            pdLo += __shfl_xor_sync(~0u, pdLo, 1); pdLo += __shfl_xor_sync(~0u, pdLo, 2);
            psHi += __shfl_xor_sync(~0u, psHi, 1); psHi += __shfl_xor_sync(~0u, psHi, 2);
            pdHi += __shfl_xor_sync(~0u, pdHi, 1); pdHi += __shfl_xor_sync(~0u, pdHi, 2);
            if (qid == 0) {
                if (rLo < N_NODES) { als[rLo * 4 + wn] = psLo; ald[rLo * 4 + wn] = pdLo; }
                if (rHi < N_NODES) { als[rHi * 4 + wn] = psHi; ald[rHi * 4 + wn] = pdHi; }
            }
        }
    }
}

// ---- GEMM2 (HMMA): A fragments loaded DIRECTLY global->registers (no smem/sync),
//      W2 in smem via cp.async. Each warp = one independent 16x64 tile. ----
__global__ __launch_bounds__(128)
void k_gemm2(const __half* __restrict__ Ah,
             __half* __restrict__ C,
             const float* __restrict__ a_s, const float* __restrict__ a_d,
             float* __restrict__ als, float* __restrict__ ald) {
    __shared__ uint4 Wsw[1024];      // 16KB

    int tid = threadIdx.x;
    int lane = tid & 31, wid = tid >> 5;
    int grp = lane >> 2, qid = lane & 3;

    // W2 -> smem (once per block)
    #pragma unroll
    for (int r = 0; r < 8; r++) {
        int u = tid + r * 128;
        int n = u >> 4, kc = u & 15;
        cp16(smem_u32(&Wsw[n * 16 + (kc ^ (n & 7))]), &g_W2h[n * 128 + kc * 8]);
    }
    asm volatile("cp.async.commit_group;");

    // A fragments: 32 independent LDG.32 per lane, two fixed rows
    int rLo = blockIdx.x * 64 + wid * 16 + grp;
    int rHi = rLo + 8;
    bool okLo = rLo < N_NODES, okHi = rHi < N_NODES;
    const __half* pLo = Ah + (size_t)rLo * 128 + qid * 2;
    const __half* pHi = Ah + (size_t)rHi * 128 + qid * 2;

    uint32_t aF[8][4];
    #pragma unroll
    for (int ks = 0; ks < 8; ks++) {
        aF[ks][0] = okLo ? *(const uint32_t*)&pLo[ks * 16]     : 0u;
        aF[ks][1] = okHi ? *(const uint32_t*)&pHi[ks * 16]     : 0u;
        aF[ks][2] = okLo ? *(const uint32_t*)&pLo[ks * 16 + 8] : 0u;
        aF[ks][3] = okHi ? *(const uint32_t*)&pHi[ks * 16 + 8] : 0u;
    }

    asm volatile("cp.async.wait_group 0;");
    __syncthreads();

    uint32_t wBase = smem_u32(Wsw);
    int bRowL = (lane & 7) + (lane >> 4) * 8;
    int bChkL = (lane >> 3) & 1;

    float acc[8][4];
    #pragma unroll
    for (int nj = 0; nj < 8; nj++)
        #pragma unroll
        for (int q = 0; q < 4; q++) acc[nj][q] = 0.f;

    #pragma unroll
    for (int ks = 0; ks < 8; ks++) {
        uint32_t bF[4][4];
        #pragma unroll
        for (int pr = 0; pr < 4; pr++) {
            int n = pr * 16 + bRowL;
            int ch = ks * 2 + bChkL;
            ldsm4(bF[pr][0], bF[pr][1], bF[pr][2], bF[pr][3],
                  wBase + (uint32_t)(n * 16 + (ch ^ (n & 7))) * 16u);
        }
        #pragma unroll
        for (int nj = 0; nj < 8; nj++)
            mma16816(acc[nj], aF[ks], &bF[nj >> 1][(nj & 1) * 2]);
    }

    float asr[8][2], adr[8][2];
    #pragma unroll
    for (int nj = 0; nj < 8; nj++) {
        int col = nj * 8 + qid * 2;
        asr[nj][0] = a_s[col]; asr[nj][1] = a_s[col + 1];
        adr[nj][0] = a_d[col]; adr[nj][1] = a_d[col + 1];
    }

    float psLo = 0.f, pdLo = 0.f, psHi = 0.f, pdHi = 0.f;
    #pragma unroll
    for (int nj = 0; nj < 8; nj++) {
        psLo += acc[nj][0] * asr[nj][0] + acc[nj][1] * asr[nj][1];
        pdLo += acc[nj][0] * adr[nj][0] + acc[nj][1] * adr[nj][1];
        psHi += acc[nj][2] * asr[nj][0] + acc[nj][3] * asr[nj][1];
        pdHi += acc[nj][2] * adr[nj][0] + acc[nj][3] * adr[nj][1];
        int col = nj * 8 + qid * 2;
        if (okLo)
            *(__half2*)&C[rLo * 64 + col] = __floats2half2_rn(acc[nj][0], acc[nj][1]);
        if (okHi)
            *(__half2*)&C[rHi * 64 + col] = __floats2half2_rn(acc[nj][2], acc[nj][3]);
    }
    psLo += __shfl_xor_sync(~0u, psLo, 1); psLo += __shfl_xor_sync(~0u, psLo, 2);
    pdLo += __shfl_xor_sync(~0u, pdLo, 1); pdLo += __shfl_xor_sync(~0u, pdLo, 2);
    psHi += __shfl_xor_sync(~0u, psHi, 1); psHi += __shfl_xor_sync(~0u, psHi, 2);
    pdHi += __shfl_xor_sync(~0u, pdHi, 1); pdHi += __shfl_xor_sync(~0u, pdHi, 2);
    if (qid == 0) {
        if (okLo) { als[rLo] = psLo; ald[rLo] = pdLo; }
        if (okHi) { als[rHi] = psHi; ald[rHi] = pdHi; }
    }
}

// ---------- layer-1 aggregation: flat 2-chunk, smem-staged (p, idx) ----------
__global__ __launch_bounds__(256)
void k_agg1(const __half* __restrict__ h, const float* __restrict__ b1,
            __half* __restrict__ out) {
    __shared__ float sp[8][64][4];
    __shared__ int   si[8][64];
    int wid = threadIdx.x >> 5, lane = threadIdx.x & 31;
    int node = blockIdx.x * 8 + wid;
    if (node >= N_NODES) return;
    int beg = node * CSR_STRIDE;
    int deg = g_cursor[node] - beg;
    float4 ald4 = *(const float4*)&g_ald1[node * 4];
    float4 alsS = *(const float4*)&g_als1[node * 4];
    float m0 = lrelu(alsS.x + ald4.x), m1 = lrelu(alsS.y + ald4.y);
    float m2 = lrelu(alsS.z + ald4.z), m3 = lrelu(alsS.w + ald4.w);
    int hl = lane >> 3;

    int idx1 = g_csr[beg + lane];
    float4 a1 = *(const float4*)&g_als1[idx1 * 4];
    bool v1 = lane < deg;
    float p10 = v1 ? __expf(lrelu(a1.x + ald4.x) - m0) : 0.f;
    float p11 = v1 ? __expf(lrelu(a1.y + ald4.y) - m1) : 0.f;
    float p12 = v1 ? __expf(lrelu(a1.z + ald4.z) - m2) : 0.f;
    float p13 = v1 ? __expf(lrelu(a1.w + ald4.w) - m3) : 0.f;
    si[wid][lane] = idx1;
    *(float4*)&sp[wid][lane][0] = make_float4(p10, p11, p12, p13);
    float dn0 = p10, dn1 = p11, dn2 = p12, dn3 = p13;

    if (deg > 32) {
        int j2 = lane + 32;
        int idx2 = g_csr[beg + j2];
        float4 a2 = *(const float4*)&g_als1[idx2 * 4];
        bool v2 = j2 < deg;
        float p20 = v2 ? __expf(lrelu(a2.x + ald4.x) - m0) : 0.f;
        float p21 = v2 ? __expf(lrelu(a2.y + ald4.y) - m1) : 0.f;
        float p22 = v2 ? __expf(lrelu(a2.z + ald4.z) - m2) : 0.f;
        float p23 = v2 ? __expf(lrelu(a2.w + ald4.w) - m3) : 0.f;
        si[wid][j2] = idx2;
        *(float4*)&sp[wid][j2][0] = make_float4(p20, p21, p22, p23);
        dn0 += p20; dn1 += p21; dn2 += p22; dn3 += p23;
    }
    __syncwarp();

    float4 acc = make_float4(0.f, 0.f, 0.f, 0.f);
    const __half* hb = h + lane * 4;
    #pragma unroll 8
    for (int t = 0; t < deg; t++) {
        int it = si[wid][t];
        float pt = sp[wid][t][hl];
        uint2 raw = *(const uint2*)&hb[it * 128];
        float2 f0 = __half22float2(*(__half2*)&raw.x);
        float2 f1 = __half22float2(*(__half2*)&raw.y);
        acc.x += pt * f0.x; acc.y += pt * f0.y;
        acc.z += pt * f1.x; acc.w += pt * f1.y;
    }

    #pragma unroll
    for (int o = 16; o > 0; o >>= 1) {
        dn0 += __shfl_xor_sync(0xffffffffu, dn0, o);
        dn1 += __shfl_xor_sync(0xffffffffu, dn1, o);
        dn2 += __shfl_xor_sync(0xffffffffu, dn2, o);
        dn3 += __shfl_xor_sync(0xffffffffu, dn3, o);
    }
    float dsel = hl == 0 ? dn0 : hl == 1 ? dn1 : hl == 2 ? dn2 : dn3;
    float inv = 1.f / dsel;
    float4 bv = *(const float4*)&b1[lane * 4];
    __align__(8) __half ho[4];
    ho[0] = __float2half_rn(fmaxf(acc.x * inv + bv.x, 0.f));
    ho[1] = __float2half_rn(fmaxf(acc.y * inv + bv.y, 0.f));
    ho[2] = __float2half_rn(fmaxf(acc.z * inv + bv.z, 0.f));
    ho[3] = __float2half_rn(fmaxf(acc.w * inv + bv.w, 0.f));
    *(uint2*)&out[node * 128 + lane * 4] = *(uint2*)ho;
}

// ---------- layer-2 aggregation: flat 2-chunk, smem-staged (p, idx) ----------
__global__ __launch_bounds__(256)
void k_agg2(const __half* __restrict__ h, const float* __restrict__ b2,
            float* __restrict__ out) {
    __shared__ float2 sp[8][64];
    int wid = threadIdx.x >> 5, lane = threadIdx.x & 31;
    int node = blockIdx.x * 8 + wid;
    if (node >= N_NODES) return;
    int beg = node * CSR_STRIDE;
    int deg = g_cursor[node] - beg;
    float ald = g_ald2[node];
    float m = lrelu(g_als2[node] + ald);

    int idx1 = g_csr[beg + lane];
    float p1 = (lane < deg) ? __expf(lrelu(g_als2[idx1] + ald) - m) : 0.f;
    sp[wid][lane] = make_float2(p1, __int_as_float(idx1));
    float dn = p1;
    if (deg > 32) {
        int j2 = lane + 32;
        int idx2 = g_csr[beg + j2];
        float p2 = (j2 < deg) ? __expf(lrelu(g_als2[idx2] + ald) - m) : 0.f;
        sp[wid][j2] = make_float2(p2, __int_as_float(idx2));
        dn += p2;
    }
    __syncwarp();

    float acc0 = 0.f, acc1 = 0.f;
    const __half* hb = h + lane * 2;
    #pragma unroll 8
    for (int t = 0; t < deg; t++) {
        float2 v = sp[wid][t];
        int it = __float_as_int(v.y);
        float2 hv = __half22float2(*(const __half2*)&hb[it * 64]);
        acc0 += v.x * hv.x;
        acc1 += v.x * hv.y;
    }
    #pragma unroll
    for (int o = 16; o > 0; o >>= 1)
        dn += __shfl_xor_sync(0xffffffffu, dn, o);
    float inv = 1.f / dn;
    float2 o2;
    o2.x = acc0 * inv + b2[lane * 2 + 0];
    o2.y = acc1 * inv + b2[lane * 2 + 1];
    *(float2*)&out[node * 64 + lane * 2] = o2;
}

// ---------------- launch ----------------
extern "C" void kernel_launch(void* const* d_in, const int* in_sizes, int n_in,
                              void* d_out, int out_size) {
    const float* x   = (const float*)d_in[0];
    const int*   ei  = (const int*)d_in[1];
    const float* W1  = (const float*)d_in[2];
    const float* as1 = (const float*)d_in[3];
    const float* ad1 = (const float*)d_in[4];
    const float* b1  = (const float*)d_in[5];
    const float* W2  = (const float*)d_in[6];
    const float* as2 = (const float*)d_in[7];
    const float* ad2 = (const float*)d_in[8];
    const float* b2  = (const float*)d_in[9];
    float* out = (float*)d_out;

    const int* src = ei;
    const int* dst = ei + N_EDGES;

    __half *h1p, *hrp, *h2p;
    float *als1p, *ald1p, *als2p, *ald2p;
    cudaGetSymbolAddress((void**)&h1p, g_h1);
    cudaGetSymbolAddress((void**)&hrp, g_hrelu);
    cudaGetSymbolAddress((void**)&h2p, g_h2);
    cudaGetSymbolAddress((void**)&als1p, g_als1);
    cudaGetSymbolAddress((void**)&ald1p, g_ald1);
    cudaGetSymbolAddress((void**)&als2p, g_als2);
    cudaGetSymbolAddress((void**)&ald2p, g_ald2);

    k_init<<<(N_NODES + 255) / 256, 256>>>(W1, W2);
    k_front<<<FRONT_BLOCKS, 256, 49152>>>(x, h1p, as1, ad1, als1p, ald1p,
                                          src, dst);
    k_agg1<<<(N_NODES + 7) / 8, 256>>>(h1p, b1, hrp);
    k_gemm2<<<NTILES1, 128>>>(hrp, h2p, as2, ad2, als2p, ald2p);
    k_agg2<<<(N_NODES + 7) / 8, 256>>>(h2p, b2, out);
}

// round 15
// speedup vs baseline: 1.0602x; 1.0602x over previous
#include <cuda_runtime.h>
#include <cuda_fp16.h>
#include <cstdint>

#define N_NODES 50000
#define N_EDGES 800000
#define CSR_STRIDE 64          /* max in-degree+1; Poisson(16) -> overflow P ~1e-22 */
#define NEG_SLOPE 0.2f
#define FRONT_BLOCKS 304
#define SCAT_BLOCKS 128
#define NTILES1 782            /* ceil(50000/64) */
#define GEMM_TILES_MAIN 704    /* 176 gemm blocks x 4 tiles; 78-tile tail on scatter blocks */

// ---------------- scratch (static device globals; no runtime alloc) ----------------
__device__ __half g_h1[N_NODES * 128];     // x @ W1 (fp16, gather source)
__device__ __half g_hrelu[N_NODES * 128];  // relu(gat1) (fp16, GEMM2 A)
__device__ __half g_h2[N_NODES * 64];      // hrelu @ W2 (fp16, gather source)
__device__ __half g_W2h[64 * 128];         // W2 fp16, [n][k]
__device__ float  g_als1[N_NODES * 4];
__device__ float  g_ald1[N_NODES * 4];
__device__ float  g_als2[N_NODES];
__device__ float  g_ald2[N_NODES];
__device__ int    g_cursor[N_NODES];
__device__ int    g_csr[N_NODES * CSR_STRIDE];
__device__ int    g_bar;                   // epoch barrier among scatter blocks

__device__ __forceinline__ float lrelu(float e) {
    return e >= 0.f ? e : NEG_SLOPE * e;
}

__device__ __forceinline__ uint32_t smem_u32(const void* p) {
    return (uint32_t)__cvta_generic_to_shared(p);
}

__device__ __forceinline__ void ldsm4(uint32_t& r0, uint32_t& r1, uint32_t& r2,
                                      uint32_t& r3, uint32_t addr) {
    asm volatile("ldmatrix.sync.aligned.m8n8.x4.shared.b16 {%0,%1,%2,%3}, [%4];"
                 : "=r"(r0), "=r"(r1), "=r"(r2), "=r"(r3) : "r"(addr));
}

__device__ __forceinline__ void mma16816(float* d, const uint32_t* a, const uint32_t* b) {
    asm volatile(
        "mma.sync.aligned.m16n8k16.row.col.f32.f16.f16.f32 "
        "{%0,%1,%2,%3}, {%4,%5,%6,%7}, {%8,%9}, {%0,%1,%2,%3};"
        : "+f"(d[0]), "+f"(d[1]), "+f"(d[2]), "+f"(d[3])
        : "r"(a[0]), "r"(a[1]), "r"(a[2]), "r"(a[3]), "r"(b[0]), "r"(b[1]));
}

__device__ __forceinline__ void cp16(uint32_t dst, const void* src) {
    asm volatile("cp.async.cg.shared.global [%0], [%1], 16;" :: "r"(dst), "l"(src));
}

// ---- fused front: cursor/W2h init + barrier + scatter (blocks 0..127),
//      HMMA GEMM1 + fused logits1 (all blocks; W1 converted inline) ----
__global__ __launch_bounds__(256)
void k_front(const float* __restrict__ A,
             const float* __restrict__ W1, const float* __restrict__ W2,
             __half* __restrict__ C,
             const float* __restrict__ a_s, const float* __restrict__ a_d,
             float* __restrict__ als, float* __restrict__ ald,
             const int* __restrict__ src, const int* __restrict__ dst) {
    extern __shared__ uint4 sm[];        // [0,1024): A 64x16; [1024,3072): W 128x16
    uint4* Asw = sm;
    uint4* Wsw = sm + 1024;

    int tid = threadIdx.x;
    int bid = blockIdx.x;

    int t0, t1;
    if (bid < SCAT_BLOCKS) {
        // ---- phase 0: init cursors + self-loops + W2h (was k_init) ----
        for (int i = bid * 256 + tid; i < N_NODES; i += SCAT_BLOCKS * 256) {
            g_csr[i * CSR_STRIDE] = i;          // appended self-loop in slot 0
            g_cursor[i] = i * CSR_STRIDE + 1;
        }
        {
            int u = bid * 256 + tid;
            if (u < 64 * 128) {                 // 8192 elems, single pass
                int k = u >> 6, n = u & 63;
                g_W2h[n * 128 + k] = __float2half_rn(W2[k * 64 + n]);
            }
        }
        __syncthreads();
        // ---- epoch barrier among the 128 scatter blocks (all wave-1 resident) ----
        if (tid == 0) {
            __threadfence();
            int v = atomicAdd(&g_bar, 1) + 1;
            int target = ((v - 1) / SCAT_BLOCKS + 1) * SCAT_BLOCKS;
            while (atomicAdd(&g_bar, 0) < target) { }
        }
        __syncthreads();

        // ---- phase 1: scatter, 4-way unrolled ----
        constexpr int STRIDE = SCAT_BLOCKS * 256;     // 32768
        int e = bid * 256 + tid;
        for (; e + 3 * STRIDE < N_EDGES; e += 4 * STRIDE) {
            int s0 = src[e],              d0 = dst[e];
            int s1 = src[e + STRIDE],     d1 = dst[e + STRIDE];
            int s2 = src[e + 2 * STRIDE], d2 = dst[e + 2 * STRIDE];
            int s3 = src[e + 3 * STRIDE], d3 = dst[e + 3 * STRIDE];
            int p0 = (s0 != d0) ? atomicAdd(&g_cursor[d0], 1) : -1;
            int p1 = (s1 != d1) ? atomicAdd(&g_cursor[d1], 1) : -1;
            int p2 = (s2 != d2) ? atomicAdd(&g_cursor[d2], 1) : -1;
            int p3 = (s3 != d3) ? atomicAdd(&g_cursor[d3], 1) : -1;
            if (p0 >= 0) g_csr[p0] = s0;
            if (p1 >= 0) g_csr[p1] = s1;
            if (p2 >= 0) g_csr[p2] = s2;
            if (p3 >= 0) g_csr[p3] = s3;
        }
        for (; e < N_EDGES; e += STRIDE) {
            int s = src[e], d = dst[e];
            if (s != d) {
                int p = atomicAdd(&g_cursor[d], 1);
                g_csr[p] = s;
            }
        }
        t0 = GEMM_TILES_MAIN + bid;
        t1 = (bid < NTILES1 - GEMM_TILES_MAIN) ? t0 + 1 : t0;
    } else {
        int nb = bid - SCAT_BLOCKS;
        t0 = nb * 4; t1 = t0 + 4;
    }
    if (t0 >= t1) return;

    // W1 fp32 -> fp16 swizzled smem (inline conversion; W1 is L2-resident)
    for (int u = tid; u < 2048; u += 256) {
        int kc = u >> 7, n = u & 127;       // consecutive n -> coalesced LDG
        __align__(16) __half tmp[8];
        #pragma unroll
        for (int i = 0; i < 8; i++)
            tmp[i] = __float2half_rn(W1[(kc * 8 + i) * 128 + n]);
        Wsw[n * 16 + (kc ^ (n & 7))] = *(const uint4*)tmp;
    }

    int lane = tid & 31, wid = tid >> 5;
    int wm = wid >> 2, wn = wid & 3;
    int grp = lane >> 2, qid = lane & 3;

    float asr[4][2], adr[4][2];
    #pragma unroll
    for (int nj = 0; nj < 4; nj++) {
        int col = wn * 32 + nj * 8 + qid * 2;
        asr[nj][0] = a_s[col]; asr[nj][1] = a_s[col + 1];
        adr[nj][0] = a_d[col]; adr[nj][1] = a_d[col + 1];
    }

    uint32_t aBase = smem_u32(Asw);
    uint32_t wBase = smem_u32(Wsw);
    int aRowL = (lane & 7) + ((lane >> 3) & 1) * 8;
    int aChkL = lane >> 4;
    int bRowL = (lane & 7) + (lane >> 4) * 8;
    int bChkL = (lane >> 3) & 1;

    for (int tile = t0; tile < t1; tile++) {
        int rowBase = tile * 64;
        __syncthreads();
        for (int u = tid; u < 1024; u += 256) {
            int r = u >> 4, c = u & 15;
            int row = rowBase + r;
            uint4 val = make_uint4(0u, 0u, 0u, 0u);
            if (row < N_NODES) {
                float4 f0 = *(const float4*)&A[row * 128 + c * 8];
                float4 f1 = *(const float4*)&A[row * 128 + c * 8 + 4];
                __align__(16) __half h8[8];
                h8[0] = __float2half_rn(f0.x); h8[1] = __float2half_rn(f0.y);
                h8[2] = __float2half_rn(f0.z); h8[3] = __float2half_rn(f0.w);
                h8[4] = __float2half_rn(f1.x); h8[5] = __float2half_rn(f1.y);
                h8[6] = __float2half_rn(f1.z); h8[7] = __float2half_rn(f1.w);
                val = *(const uint4*)h8;
            }
            Asw[r * 16 + (c ^ (r & 7))] = val;
        }
        __syncthreads();

        float acc[2][4][4];
        #pragma unroll
        for (int mi = 0; mi < 2; mi++)
            #pragma unroll
            for (int nj = 0; nj < 4; nj++)
                #pragma unroll
                for (int q = 0; q < 4; q++) acc[mi][nj][q] = 0.f;

        #pragma unroll
        for (int ks = 0; ks < 8; ks++) {
            uint32_t aF[2][4], bF[2][4];
            #pragma unroll
            for (int mi = 0; mi < 2; mi++) {
                int row = wm * 32 + mi * 16 + aRowL;
                int ch = ks * 2 + aChkL;
                ldsm4(aF[mi][0], aF[mi][1], aF[mi][2], aF[mi][3],
                      aBase + (uint32_t)(row * 16 + (ch ^ (row & 7))) * 16u);
            }
            #pragma unroll
            for (int pr = 0; pr < 2; pr++) {
                int n = wn * 32 + pr * 16 + bRowL;
                int ch = ks * 2 + bChkL;
                ldsm4(bF[pr][0], bF[pr][1], bF[pr][2], bF[pr][3],
                      wBase + (uint32_t)(n * 16 + (ch ^ (n & 7))) * 16u);
            }
            #pragma unroll
            for (int mi = 0; mi < 2; mi++)
                #pragma unroll
                for (int nj = 0; nj < 4; nj++)
                    mma16816(acc[mi][nj], aF[mi], &bF[nj >> 1][(nj & 1) * 2]);
        }

        #pragma unroll
        for (int mi = 0; mi < 2; mi++) {
            int rLo = rowBase + wm * 32 + mi * 16 + grp;
            int rHi = rLo + 8;
            float psLo = 0.f, pdLo = 0.f, psHi = 0.f, pdHi = 0.f;
            #pragma unroll
            for (int nj = 0; nj < 4; nj++) {
                psLo += acc[mi][nj][0] * asr[nj][0] + acc[mi][nj][1] * asr[nj][1];
                pdLo += acc[mi][nj][0] * adr[nj][0] + acc[mi][nj][1] * adr[nj][1];
                psHi += acc[mi][nj][2] * asr[nj][0] + acc[mi][nj][3] * asr[nj][1];
                pdHi += acc[mi][nj][2] * adr[nj][0] + acc[mi][nj][3] * adr[nj][1];
                int col = wn * 32 + nj * 8 + qid * 2;
                if (rLo < N_NODES)
                    *(__half2*)&C[rLo * 128 + col] =
                        __floats2half2_rn(acc[mi][nj][0], acc[mi][nj][1]);
                if (rHi < N_NODES)
                    *(__half2*)&C[rHi * 128 + col] =
                        __floats2half2_rn(acc[mi][nj][2], acc[mi][nj][3]);
            }
            psLo += __shfl_xor_sync(~0u, psLo, 1); psLo += __shfl_xor_sync(~0u, psLo, 2);
            pdLo += __shfl_xor_sync(~0u, pdLo, 1); pdLo += __shfl_xor_sync(~0u, pdLo, 2);
            psHi += __shfl_xor_sync(~0u, psHi, 1); psHi += __shfl_xor_sync(~0u, psHi, 2);
            pdHi += __shfl_xor_sync(~0u, pdHi, 1); pdHi += __shfl_xor_sync(~0u, pdHi, 2);
            if (qid == 0) {
                if (rLo < N_NODES) { als[rLo * 4 + wn] = psLo; ald[rLo * 4 + wn] = pdLo; }
                if (rHi < N_NODES) { als[rHi * 4 + wn] = psHi; ald[rHi * 4 + wn] = pdHi; }
            }
        }
    }
}

// ---- GEMM2 (HMMA): 2 tiles per block, double-buffered A, W loaded once (R13) ----
__global__ __launch_bounds__(128)
void k_gemm2(const __half* __restrict__ Ah,
             __half* __restrict__ C,
             const float* __restrict__ a_s, const float* __restrict__ a_d,
             float* __restrict__ als, float* __restrict__ ald) {
    __shared__ uint4 Wsw[1024];      // 16KB
    __shared__ uint4 Asw[2][1024];   // 2 x 16KB

    int tid = threadIdx.x;
    int tileBase = blockIdx.x * 2;

    #pragma unroll
    for (int r = 0; r < 8; r++) {
        int u = tid + r * 128;
        int n = u >> 4, kc = u & 15;
        cp16(smem_u32(&Wsw[n * 16 + (kc ^ (n & 7))]), &g_W2h[n * 128 + kc * 8]);
    }
    asm volatile("cp.async.commit_group;");

    #pragma unroll
    for (int r = 0; r < 8; r++) {
        int u = tid + r * 128;
        int rr = u >> 4, c = u & 15;
        int row = tileBase * 64 + rr;
        if (row < N_NODES)
            cp16(smem_u32(&Asw[0][rr * 16 + (c ^ (rr & 7))]), &Ah[row * 128 + c * 8]);
        else
            Asw[0][rr * 16 + (c ^ (rr & 7))] = make_uint4(0u, 0u, 0u, 0u);
    }
    asm volatile("cp.async.commit_group;");

    int lane = tid & 31, wid = tid >> 5;
    int grp = lane >> 2, qid = lane & 3;
    uint32_t wBase = smem_u32(Wsw);
    int aRowL = (lane & 7) + ((lane >> 3) & 1) * 8;
    int aChkL = lane >> 4;
    int bRowL = (lane & 7) + (lane >> 4) * 8;
    int bChkL = (lane >> 3) & 1;

    float asr[8][2], adr[8][2];
    #pragma unroll
    for (int nj = 0; nj < 8; nj++) {
        int col = nj * 8 + qid * 2;
        asr[nj][0] = a_s[col]; asr[nj][1] = a_s[col + 1];
        adr[nj][0] = a_d[col]; adr[nj][1] = a_d[col + 1];
    }

    #pragma unroll
    for (int tt = 0; tt < 2; tt++) {
        int tile = tileBase + tt;
        int rowBase = tile * 64;

        if (tt == 0) {
            #pragma unroll
            for (int r = 0; r < 8; r++) {
                int u = tid + r * 128;
                int rr = u >> 4, c = u & 15;
                int row = (tileBase + 1) * 64 + rr;
                if (row < N_NODES)
                    cp16(smem_u32(&Asw[1][rr * 16 + (c ^ (rr & 7))]),
                         &Ah[row * 128 + c * 8]);
                else
                    Asw[1][rr * 16 + (c ^ (rr & 7))] = make_uint4(0u, 0u, 0u, 0u);
            }
            asm volatile("cp.async.commit_group;");
            asm volatile("cp.async.wait_group 1;");   // W + A0 done
        } else {
            asm volatile("cp.async.wait_group 0;");   // A1 done
        }
        __syncthreads();

        uint32_t aBase = smem_u32(Asw[tt]);
        float acc[8][4];
        #pragma unroll
        for (int nj = 0; nj < 8; nj++)
            #pragma unroll
            for (int q = 0; q < 4; q++) acc[nj][q] = 0.f;

        #pragma unroll
        for (int ks = 0; ks < 8; ks++) {
            uint32_t aF[4], bF[4][4];
            {
                int row = wid * 16 + aRowL;
                int ch = ks * 2 + aChkL;
                ldsm4(aF[0], aF[1], aF[2], aF[3],
                      aBase + (uint32_t)(row * 16 + (ch ^ (row & 7))) * 16u);
            }
            #pragma unroll
            for (int pr = 0; pr < 4; pr++) {
                int n = pr * 16 + bRowL;
                int ch = ks * 2 + bChkL;
                ldsm4(bF[pr][0], bF[pr][1], bF[pr][2], bF[pr][3],
                      wBase + (uint32_t)(n * 16 + (ch ^ (n & 7))) * 16u);
            }
            #pragma unroll
            for (int nj = 0; nj < 8; nj++)
                mma16816(acc[nj], aF, &bF[nj >> 1][(nj & 1) * 2]);
        }

        int rLo = rowBase + wid * 16 + grp;
        int rHi = rLo + 8;
        float psLo = 0.f, pdLo = 0.f, psHi = 0.f, pdHi = 0.f;
        #pragma unroll
        for (int nj = 0; nj < 8; nj++) {
            psLo += acc[nj][0] * asr[nj][0] + acc[nj][1] * asr[nj][1];
            pdLo += acc[nj][0] * adr[nj][0] + acc[nj][1] * adr[nj][1];
            psHi += acc[nj][2] * asr[nj][0] + acc[nj][3] * asr[nj][1];
            pdHi += acc[nj][2] * adr[nj][0] + acc[nj][3] * adr[nj][1];
            int col = nj * 8 + qid * 2;
            if (rLo < N_NODES)
                *(__half2*)&C[rLo * 64 + col] = __floats2half2_rn(acc[nj][0], acc[nj][1]);
            if (rHi < N_NODES)
                *(__half2*)&C[rHi * 64 + col] = __floats2half2_rn(acc[nj][2], acc[nj][3]);
        }
        psLo += __shfl_xor_sync(~0u, psLo, 1); psLo += __shfl_xor_sync(~0u, psLo, 2);
        pdLo += __shfl_xor_sync(~0u, pdLo, 1); pdLo += __shfl_xor_sync(~0u, pdLo, 2);
        psHi += __shfl_xor_sync(~0u, psHi, 1); psHi += __shfl_xor_sync(~0u, psHi, 2);
        pdHi += __shfl_xor_sync(~0u, pdHi, 1); pdHi += __shfl_xor_sync(~0u, pdHi, 2);
        if (qid == 0) {
            if (rLo < N_NODES) { als[rLo] = psLo; ald[rLo] = pdLo; }
            if (rHi < N_NODES) { als[rHi] = psHi; ald[rHi] = pdHi; }
        }
    }
}

// ---------- layer-1 aggregation: flat 2-chunk, smem-staged (p, idx) ----------
__global__ __launch_bounds__(256)
void k_agg1(const __half* __restrict__ h, const float* __restrict__ b1,
            __half* __restrict__ out) {
    __shared__ float sp[8][64][4];
    __shared__ int   si[8][64];
    int wid = threadIdx.x >> 5, lane = threadIdx.x & 31;
    int node = blockIdx.x * 8 + wid;
    if (node >= N_NODES) return;
    int beg = node * CSR_STRIDE;
    int deg = g_cursor[node] - beg;
    float4 ald4 = *(const float4*)&g_ald1[node * 4];
    float4 alsS = *(const float4*)&g_als1[node * 4];
    float m0 = lrelu(alsS.x + ald4.x), m1 = lrelu(alsS.y + ald4.y);
    float m2 = lrelu(alsS.z + ald4.z), m3 = lrelu(alsS.w + ald4.w);
    int hl = lane >> 3;

    int idx1 = g_csr[beg + lane];
    float4 a1 = *(const float4*)&g_als1[idx1 * 4];
    bool v1 = lane < deg;
    float p10 = v1 ? __expf(lrelu(a1.x + ald4.x) - m0) : 0.f;
    float p11 = v1 ? __expf(lrelu(a1.y + ald4.y) - m1) : 0.f;
    float p12 = v1 ? __expf(lrelu(a1.z + ald4.z) - m2) : 0.f;
    float p13 = v1 ? __expf(lrelu(a1.w + ald4.w) - m3) : 0.f;
    si[wid][lane] = idx1;
    *(float4*)&sp[wid][lane][0] = make_float4(p10, p11, p12, p13);
    float dn0 = p10, dn1 = p11, dn2 = p12, dn3 = p13;

    if (deg > 32) {
        int j2 = lane + 32;
        int idx2 = g_csr[beg + j2];
        float4 a2 = *(const float4*)&g_als1[idx2 * 4];
        bool v2 = j2 < deg;
        float p20 = v2 ? __expf(lrelu(a2.x + ald4.x) - m0) : 0.f;
        float p21 = v2 ? __expf(lrelu(a2.y + ald4.y) - m1) : 0.f;
        float p22 = v2 ? __expf(lrelu(a2.z + ald4.z) - m2) : 0.f;
        float p23 = v2 ? __expf(lrelu(a2.w + ald4.w) - m3) : 0.f;
        si[wid][j2] = idx2;
        *(float4*)&sp[wid][j2][0] = make_float4(p20, p21, p22, p23);
        dn0 += p20; dn1 += p21; dn2 += p22; dn3 += p23;
    }
    __syncwarp();

    float4 acc = make_float4(0.f, 0.f, 0.f, 0.f);
    const __half* hb = h + lane * 4;
    #pragma unroll 8
    for (int t = 0; t < deg; t++) {
        int it = si[wid][t];
        float pt = sp[wid][t][hl];
        uint2 raw = *(const uint2*)&hb[it * 128];
        float2 f0 = __half22float2(*(__half2*)&raw.x);
        float2 f1 = __half22float2(*(__half2*)&raw.y);
        acc.x += pt * f0.x; acc.y += pt * f0.y;
        acc.z += pt * f1.x; acc.w += pt * f1.y;
    }

    #pragma unroll
    for (int o = 16; o > 0; o >>= 1) {
        dn0 += __shfl_xor_sync(0xffffffffu, dn0, o);
        dn1 += __shfl_xor_sync(0xffffffffu, dn1, o);
        dn2 += __shfl_xor_sync(0xffffffffu, dn2, o);
        dn3 += __shfl_xor_sync(0xffffffffu, dn3, o);
    }
    float dsel = hl == 0 ? dn0 : hl == 1 ? dn1 : hl == 2 ? dn2 : dn3;
    float inv = 1.f / dsel;
    float4 bv = *(const float4*)&b1[lane * 4];
    __align__(8) __half ho[4];
    ho[0] = __float2half_rn(fmaxf(acc.x * inv + bv.x, 0.f));
    ho[1] = __float2half_rn(fmaxf(acc.y * inv + bv.y, 0.f));
    ho[2] = __float2half_rn(fmaxf(acc.z * inv + bv.z, 0.f));
    ho[3] = __float2half_rn(fmaxf(acc.w * inv + bv.w, 0.f));
    *(uint2*)&out[node * 128 + lane * 4] = *(uint2*)ho;
}

// ---------- layer-2 aggregation: flat 2-chunk, smem-staged (p, idx) ----------
__global__ __launch_bounds__(256)
void k_agg2(const __half* __restrict__ h, const float* __restrict__ b2,
            float* __restrict__ out) {
    __shared__ float2 sp[8][64];
    int wid = threadIdx.x >> 5, lane = threadIdx.x & 31;
    int node = blockIdx.x * 8 + wid;
    if (node >= N_NODES) return;
    int beg = node * CSR_STRIDE;
    int deg = g_cursor[node] - beg;
    float ald = g_ald2[node];
    float m = lrelu(g_als2[node] + ald);

    int idx1 = g_csr[beg + lane];
    float p1 = (lane < deg) ? __expf(lrelu(g_als2[idx1] + ald) - m) : 0.f;
    sp[wid][lane] = make_float2(p1, __int_as_float(idx1));
    float dn = p1;
    if (deg > 32) {
        int j2 = lane + 32;
        int idx2 = g_csr[beg + j2];
        float p2 = (j2 < deg) ? __expf(lrelu(g_als2[idx2] + ald) - m) : 0.f;
        sp[wid][j2] = make_float2(p2, __int_as_float(idx2));
        dn += p2;
    }
    __syncwarp();

    float acc0 = 0.f, acc1 = 0.f;
    const __half* hb = h + lane * 2;
    #pragma unroll 8
    for (int t = 0; t < deg; t++) {
        float2 v = sp[wid][t];
        int it = __float_as_int(v.y);
        float2 hv = __half22float2(*(const __half2*)&hb[it * 64]);
        acc0 += v.x * hv.x;
        acc1 += v.x * hv.y;
    }
    #pragma unroll
    for (int o = 16; o > 0; o >>= 1)
        dn += __shfl_xor_sync(0xffffffffu, dn, o);
    float inv = 1.f / dn;
    float2 o2;
    o2.x = acc0 * inv + b2[lane * 2 + 0];
    o2.y = acc1 * inv + b2[lane * 2 + 1];
    *(float2*)&out[node * 64 + lane * 2] = o2;
}

// ---------------- launch ----------------
extern "C" void kernel_launch(void* const* d_in, const int* in_sizes, int n_in,
                              void* d_out, int out_size) {
    const float* x   = (const float*)d_in[0];
    const int*   ei  = (const int*)d_in[1];
    const float* W1  = (const float*)d_in[2];
    const float* as1 = (const float*)d_in[3];
    const float* ad1 = (const float*)d_in[4];
    const float* b1  = (const float*)d_in[5];
    const float* W2  = (const float*)d_in[6];
    const float* as2 = (const float*)d_in[7];
    const float* ad2 = (const float*)d_in[8];
    const float* b2  = (const float*)d_in[9];
    float* out = (float*)d_out;

    const int* src = ei;
    const int* dst = ei + N_EDGES;

    __half *h1p, *hrp, *h2p;
    float *als1p, *ald1p, *als2p, *ald2p;
    cudaGetSymbolAddress((void**)&h1p, g_h1);
    cudaGetSymbolAddress((void**)&hrp, g_hrelu);
    cudaGetSymbolAddress((void**)&h2p, g_h2);
    cudaGetSymbolAddress((void**)&als1p, g_als1);
    cudaGetSymbolAddress((void**)&ald1p, g_ald1);
    cudaGetSymbolAddress((void**)&als2p, g_als2);
    cudaGetSymbolAddress((void**)&ald2p, g_ald2);

    k_front<<<FRONT_BLOCKS, 256, 49152>>>(x, W1, W2, h1p, as1, ad1,
                                          als1p, ald1p, src, dst);
    k_agg1<<<(N_NODES + 7) / 8, 256>>>(h1p, b1, hrp);
    k_gemm2<<<NTILES1 / 2, 128>>>(hrp, h2p, as2, ad2, als2p, ald2p);
    k_agg2<<<(N_NODES + 7) / 8, 256>>>(h2p, b2, out);
}

// round 16
// speedup vs baseline: 1.0685x; 1.0078x over previous
#include <cuda_runtime.h>
#include <cuda_fp16.h>
#include <cstdint>

#define N_NODES 50000
#define N_EDGES 800000
#define CSR_STRIDE 64          /* max in-degree+1; Poisson(16) -> overflow P ~1e-22 */
#define NEG_SLOPE 0.2f
#define FRONT_BLOCKS 304
#define SCAT_BLOCKS 128
#define NTILES1 782            /* ceil(50000/64) */
#define GEMM_TILES_MAIN 704    /* 176 gemm blocks x 4 tiles; 78-tile tail on scatter blocks */

// ---------------- scratch (static device globals; no runtime alloc) ----------------
__device__ __half g_h1[N_NODES * 128];     // x @ W1 (fp16, gather source)
__device__ __half g_hrelu[N_NODES * 128];  // relu(gat1) (fp16, GEMM2 A)
__device__ float  g_h2[N_NODES * 64];      // hrelu @ W2 (fp32: agg2 is issue-bound, not BW)
__device__ __half g_W2h[64 * 128];         // W2 fp16, [n][k]
__device__ float  g_als1[N_NODES * 4];
__device__ float  g_ald1[N_NODES * 4];
__device__ float  g_als2[N_NODES];
__device__ float  g_ald2[N_NODES];
__device__ int    g_cursor[N_NODES];
__device__ int    g_csr[N_NODES * CSR_STRIDE];
__device__ int    g_bar;                   // epoch barrier among scatter blocks

__device__ __forceinline__ float lrelu(float e) {
    return e >= 0.f ? e : NEG_SLOPE * e;
}

__device__ __forceinline__ uint32_t smem_u32(const void* p) {
    return (uint32_t)__cvta_generic_to_shared(p);
}

__device__ __forceinline__ void ldsm4(uint32_t& r0, uint32_t& r1, uint32_t& r2,
                                      uint32_t& r3, uint32_t addr) {
    asm volatile("ldmatrix.sync.aligned.m8n8.x4.shared.b16 {%0,%1,%2,%3}, [%4];"
                 : "=r"(r0), "=r"(r1), "=r"(r2), "=r"(r3) : "r"(addr));
}

__device__ __forceinline__ void mma16816(float* d, const uint32_t* a, const uint32_t* b) {
    asm volatile(
        "mma.sync.aligned.m16n8k16.row.col.f32.f16.f16.f32 "
        "{%0,%1,%2,%3}, {%4,%5,%6,%7}, {%8,%9}, {%0,%1,%2,%3};"
        : "+f"(d[0]), "+f"(d[1]), "+f"(d[2]), "+f"(d[3])
        : "r"(a[0]), "r"(a[1]), "r"(a[2]), "r"(a[3]), "r"(b[0]), "r"(b[1]));
}

__device__ __forceinline__ void cp16(uint32_t dst, const void* src) {
    asm volatile("cp.async.cg.shared.global [%0], [%1], 16;" :: "r"(dst), "l"(src));
}

// ---- fused front: cursor/W2h init + barrier + scatter (blocks 0..127),
//      HMMA GEMM1 + fused logits1 (all blocks; W1 converted inline) ----
__global__ __launch_bounds__(256)
void k_front(const float* __restrict__ A,
             const float* __restrict__ W1, const float* __restrict__ W2,
             __half* __restrict__ C,
             const float* __restrict__ a_s, const float* __restrict__ a_d,
             float* __restrict__ als, float* __restrict__ ald,
             const int* __restrict__ src, const int* __restrict__ dst) {
    extern __shared__ uint4 sm[];        // [0,1024): A 64x16; [1024,3072): W 128x16
    uint4* Asw = sm;
    uint4* Wsw = sm + 1024;

    int tid = threadIdx.x;
    int bid = blockIdx.x;

    int t0, t1;
    if (bid < SCAT_BLOCKS) {
        // ---- phase 0: init cursors + self-loops + W2h ----
        for (int i = bid * 256 + tid; i < N_NODES; i += SCAT_BLOCKS * 256) {
            g_csr[i * CSR_STRIDE] = i;          // appended self-loop in slot 0
            g_cursor[i] = i * CSR_STRIDE + 1;
        }
        {
            int u = bid * 256 + tid;
            if (u < 64 * 128) {
                int k = u >> 6, n = u & 63;
                g_W2h[n * 128 + k] = __float2half_rn(W2[k * 64 + n]);
            }
        }
        __syncthreads();
        // ---- epoch barrier among the 128 scatter blocks (all wave-1 resident) ----
        if (tid == 0) {
            __threadfence();
            int v = atomicAdd(&g_bar, 1) + 1;
            int target = ((v - 1) / SCAT_BLOCKS + 1) * SCAT_BLOCKS;
            while (atomicAdd(&g_bar, 0) < target) { }
        }
        __syncthreads();

        // ---- phase 1: scatter, 4-way unrolled ----
        constexpr int STRIDE = SCAT_BLOCKS * 256;     // 32768
        int e = bid * 256 + tid;
        for (; e + 3 * STRIDE < N_EDGES; e += 4 * STRIDE) {
            int s0 = src[e],              d0 = dst[e];
            int s1 = src[e + STRIDE],     d1 = dst[e + STRIDE];
            int s2 = src[e + 2 * STRIDE], d2 = dst[e + 2 * STRIDE];
            int s3 = src[e + 3 * STRIDE], d3 = dst[e + 3 * STRIDE];
            int p0 = (s0 != d0) ? atomicAdd(&g_cursor[d0], 1) : -1;
            int p1 = (s1 != d1) ? atomicAdd(&g_cursor[d1], 1) : -1;
            int p2 = (s2 != d2) ? atomicAdd(&g_cursor[d2], 1) : -1;
            int p3 = (s3 != d3) ? atomicAdd(&g_cursor[d3], 1) : -1;
            if (p0 >= 0) g_csr[p0] = s0;
            if (p1 >= 0) g_csr[p1] = s1;
            if (p2 >= 0) g_csr[p2] = s2;
            if (p3 >= 0) g_csr[p3] = s3;
        }
        for (; e < N_EDGES; e += STRIDE) {
            int s = src[e], d = dst[e];
            if (s != d) {
                int p = atomicAdd(&g_cursor[d], 1);
                g_csr[p] = s;
            }
        }
        t0 = GEMM_TILES_MAIN + bid;
        t1 = (bid < NTILES1 - GEMM_TILES_MAIN) ? t0 + 1 : t0;
    } else {
        int nb = bid - SCAT_BLOCKS;
        t0 = nb * 4; t1 = t0 + 4;
    }
    if (t0 >= t1) return;

    // W1 fp32 -> fp16 swizzled smem (inline conversion; W1 is L2-resident)
    for (int u = tid; u < 2048; u += 256) {
        int kc = u >> 7, n = u & 127;
        __align__(16) __half tmp[8];
        #pragma unroll
        for (int i = 0; i < 8; i++)
            tmp[i] = __float2half_rn(W1[(kc * 8 + i) * 128 + n]);
        Wsw[n * 16 + (kc ^ (n & 7))] = *(const uint4*)tmp;
    }

    int lane = tid & 31, wid = tid >> 5;
    int wm = wid >> 2, wn = wid & 3;
    int grp = lane >> 2, qid = lane & 3;

    float asr[4][2], adr[4][2];
    #pragma unroll
    for (int nj = 0; nj < 4; nj++) {
        int col = wn * 32 + nj * 8 + qid * 2;
        asr[nj][0] = a_s[col]; asr[nj][1] = a_s[col + 1];
        adr[nj][0] = a_d[col]; adr[nj][1] = a_d[col + 1];
    }

    uint32_t aBase = smem_u32(Asw);
    uint32_t wBase = smem_u32(Wsw);
    int aRowL = (lane & 7) + ((lane >> 3) & 1) * 8;
    int aChkL = lane >> 4;
    int bRowL = (lane & 7) + (lane >> 4) * 8;
    int bChkL = (lane >> 3) & 1;

    for (int tile = t0; tile < t1; tile++) {
        int rowBase = tile * 64;
        __syncthreads();
        for (int u = tid; u < 1024; u += 256) {
            int r = u >> 4, c = u & 15;
            int row = rowBase + r;
            uint4 val = make_uint4(0u, 0u, 0u, 0u);
            if (row < N_NODES) {
                float4 f0 = *(const float4*)&A[row * 128 + c * 8];
                float4 f1 = *(const float4*)&A[row * 128 + c * 8 + 4];
                __align__(16) __half h8[8];
                h8[0] = __float2half_rn(f0.x); h8[1] = __float2half_rn(f0.y);
                h8[2] = __float2half_rn(f0.z); h8[3] = __float2half_rn(f0.w);
                h8[4] = __float2half_rn(f1.x); h8[5] = __float2half_rn(f1.y);
                h8[6] = __float2half_rn(f1.z); h8[7] = __float2half_rn(f1.w);
                val = *(const uint4*)h8;
            }
            Asw[r * 16 + (c ^ (r & 7))] = val;
        }
        __syncthreads();

        float acc[2][4][4];
        #pragma unroll
        for (int mi = 0; mi < 2; mi++)
            #pragma unroll
            for (int nj = 0; nj < 4; nj++)
                #pragma unroll
                for (int q = 0; q < 4; q++) acc[mi][nj][q] = 0.f;

        #pragma unroll
        for (int ks = 0; ks < 8; ks++) {
            uint32_t aF[2][4], bF[2][4];
            #pragma unroll
            for (int mi = 0; mi < 2; mi++) {
                int row = wm * 32 + mi * 16 + aRowL;
                int ch = ks * 2 + aChkL;
                ldsm4(aF[mi][0], aF[mi][1], aF[mi][2], aF[mi][3],
                      aBase + (uint32_t)(row * 16 + (ch ^ (row & 7))) * 16u);
            }
            #pragma unroll
            for (int pr = 0; pr < 2; pr++) {
                int n = wn * 32 + pr * 16 + bRowL;
                int ch = ks * 2 + bChkL;
                ldsm4(bF[pr][0], bF[pr][1], bF[pr][2], bF[pr][3],
                      wBase + (uint32_t)(n * 16 + (ch ^ (n & 7))) * 16u);
            }
            #pragma unroll
            for (int mi = 0; mi < 2; mi++)
                #pragma unroll
                for (int nj = 0; nj < 4; nj++)
                    mma16816(acc[mi][nj], aF[mi], &bF[nj >> 1][(nj & 1) * 2]);
        }

        #pragma unroll
        for (int mi = 0; mi < 2; mi++) {
            int rLo = rowBase + wm * 32 + mi * 16 + grp;
            int rHi = rLo + 8;
            float psLo = 0.f, pdLo = 0.f, psHi = 0.f, pdHi = 0.f;
            #pragma unroll
            for (int nj = 0; nj < 4; nj++) {
                psLo += acc[mi][nj][0] * asr[nj][0] + acc[mi][nj][1] * asr[nj][1];
                pdLo += acc[mi][nj][0] * adr[nj][0] + acc[mi][nj][1] * adr[nj][1];
                psHi += acc[mi][nj][2] * asr[nj][0] + acc[mi][nj][3] * asr[nj][1];
                pdHi += acc[mi][nj][2] * adr[nj][0] + acc[mi][nj][3] * adr[nj][1];
                int col = wn * 32 + nj * 8 + qid * 2;
                if (rLo < N_NODES)
                    *(__half2*)&C[rLo * 128 + col] =
                        __floats2half2_rn(acc[mi][nj][0], acc[mi][nj][1]);
                if (rHi < N_NODES)
                    *(__half2*)&C[rHi * 128 + col] =
                        __floats2half2_rn(acc[mi][nj][2], acc[mi][nj][3]);
            }
            psLo += __shfl_xor_sync(~0u, psLo, 1); psLo += __shfl_xor_sync(~0u, psLo, 2);
            pdLo += __shfl_xor_sync(~0u, pdLo, 1); pdLo += __shfl_xor_sync(~0u, pdLo, 2);
            psHi += __shfl_xor_sync(~0u, psHi, 1); psHi += __shfl_xor_sync(~0u, psHi, 2);
            pdHi += __shfl_xor_sync(~0u, pdHi, 1); pdHi += __shfl_xor_sync(~0u, pdHi, 2);
            if (qid == 0) {
                if (rLo < N_NODES) { als[rLo * 4 + wn] = psLo; ald[rLo * 4 + wn] = pdLo; }
                if (rHi < N_NODES) { als[rHi * 4 + wn] = psHi; ald[rHi * 4 + wn] = pdHi; }
            }
        }
    }
}

// ---- GEMM2 (HMMA): 2 tiles per block, double-buffered A, fp32 output ----
__global__ __launch_bounds__(128)
void k_gemm2(const __half* __restrict__ Ah,
             float* __restrict__ C,
             const float* __restrict__ a_s, const float* __restrict__ a_d,
             float* __restrict__ als, float* __restrict__ ald) {
    __shared__ uint4 Wsw[1024];      // 16KB
    __shared__ uint4 Asw[2][1024];   // 2 x 16KB

    int tid = threadIdx.x;
    int tileBase = blockIdx.x * 2;

    #pragma unroll
    for (int r = 0; r < 8; r++) {
        int u = tid + r * 128;
        int n = u >> 4, kc = u & 15;
        cp16(smem_u32(&Wsw[n * 16 + (kc ^ (n & 7))]), &g_W2h[n * 128 + kc * 8]);
    }
    asm volatile("cp.async.commit_group;");

    #pragma unroll
    for (int r = 0; r < 8; r++) {
        int u = tid + r * 128;
        int rr = u >> 4, c = u & 15;
        int row = tileBase * 64 + rr;
        if (row < N_NODES)
            cp16(smem_u32(&Asw[0][rr * 16 + (c ^ (rr & 7))]), &Ah[row * 128 + c * 8]);
        else
            Asw[0][rr * 16 + (c ^ (rr & 7))] = make_uint4(0u, 0u, 0u, 0u);
    }
    asm volatile("cp.async.commit_group;");

    int lane = tid & 31, wid = tid >> 5;
    int grp = lane >> 2, qid = lane & 3;
    uint32_t wBase = smem_u32(Wsw);
    int aRowL = (lane & 7) + ((lane >> 3) & 1) * 8;
    int aChkL = lane >> 4;
    int bRowL = (lane & 7) + (lane >> 4) * 8;
    int bChkL = (lane >> 3) & 1;

    float asr[8][2], adr[8][2];
    #pragma unroll
    for (int nj = 0; nj < 8; nj++) {
        int col = nj * 8 + qid * 2;
        asr[nj][0] = a_s[col]; asr[nj][1] = a_s[col + 1];
        adr[nj][0] = a_d[col]; adr[nj][1] = a_d[col + 1];
    }

    #pragma unroll
    for (int tt = 0; tt < 2; tt++) {
        int tile = tileBase + tt;
        int rowBase = tile * 64;

        if (tt == 0) {
            #pragma unroll
            for (int r = 0; r < 8; r++) {
                int u = tid + r * 128;
                int rr = u >> 4, c = u & 15;
                int row = (tileBase + 1) * 64 + rr;
                if (row < N_NODES)
                    cp16(smem_u32(&Asw[1][rr * 16 + (c ^ (rr & 7))]),
                         &Ah[row * 128 + c * 8]);
                else
                    Asw[1][rr * 16 + (c ^ (rr & 7))] = make_uint4(0u, 0u, 0u, 0u);
            }
            asm volatile("cp.async.commit_group;");
            asm volatile("cp.async.wait_group 1;");   // W + A0 done
        } else {
            asm volatile("cp.async.wait_group 0;");   // A1 done
        }
        __syncthreads();

        uint32_t aBase = smem_u32(Asw[tt]);
        float acc[8][4];
        #pragma unroll
        for (int nj = 0; nj < 8; nj++)
            #pragma unroll
            for (int q = 0; q < 4; q++) acc[nj][q] = 0.f;

        #pragma unroll
        for (int ks = 0; ks < 8; ks++) {
            uint32_t aF[4], bF[4][4];
            {
                int row = wid * 16 + aRowL;
                int ch = ks * 2 + aChkL;
                ldsm4(aF[0], aF[1], aF[2], aF[3],
                      aBase + (uint32_t)(row * 16 + (ch ^ (row & 7))) * 16u);
            }
            #pragma unroll
            for (int pr = 0; pr < 4; pr++) {
                int n = pr * 16 + bRowL;
                int ch = ks * 2 + bChkL;
                ldsm4(bF[pr][0], bF[pr][1], bF[pr][2], bF[pr][3],
                      wBase + (uint32_t)(n * 16 + (ch ^ (n & 7))) * 16u);
            }
            #pragma unroll
            for (int nj = 0; nj < 8; nj++)
                mma16816(acc[nj], aF, &bF[nj >> 1][(nj & 1) * 2]);
        }

        int rLo = rowBase + wid * 16 + grp;
        int rHi = rLo + 8;
        float psLo = 0.f, pdLo = 0.f, psHi = 0.f, pdHi = 0.f;
        #pragma unroll
        for (int nj = 0; nj < 8; nj++) {
            psLo += acc[nj][0] * asr[nj][0] + acc[nj][1] * asr[nj][1];
            pdLo += acc[nj][0] * adr[nj][0] + acc[nj][1] * adr[nj][1];
            psHi += acc[nj][2] * asr[nj][0] + acc[nj][3] * asr[nj][1];
            pdHi += acc[nj][2] * adr[nj][0] + acc[nj][3] * adr[nj][1];
            int col = nj * 8 + qid * 2;
            if (rLo < N_NODES)
                *(float2*)&C[rLo * 64 + col] = make_float2(acc[nj][0], acc[nj][1]);
            if (rHi < N_NODES)
                *(float2*)&C[rHi * 64 + col] = make_float2(acc[nj][2], acc[nj][3]);
        }
        psLo += __shfl_xor_sync(~0u, psLo, 1); psLo += __shfl_xor_sync(~0u, psLo, 2);
        pdLo += __shfl_xor_sync(~0u, pdLo, 1); pdLo += __shfl_xor_sync(~0u, pdLo, 2);
        psHi += __shfl_xor_sync(~0u, psHi, 1); psHi += __shfl_xor_sync(~0u, psHi, 2);
        pdHi += __shfl_xor_sync(~0u, pdHi, 1); pdHi += __shfl_xor_sync(~0u, pdHi, 2);
        if (qid == 0) {
            if (rLo < N_NODES) { als[rLo] = psLo; ald[rLo] = pdLo; }
            if (rHi < N_NODES) { als[rHi] = psHi; ald[rHi] = pdHi; }
        }
    }
}

// ---------- layer-1 aggregation: flat 2-chunk, smem-staged (p, prescaled idx) ------
__global__ __launch_bounds__(256)
void k_agg1(const __half* __restrict__ h, const float* __restrict__ b1,
            __half* __restrict__ out) {
    __shared__ float sp[8][64][4];
    __shared__ int   si[8][64];
    int wid = threadIdx.x >> 5, lane = threadIdx.x & 31;
    int node = blockIdx.x * 8 + wid;
    if (node >= N_NODES) return;
    int beg = node * CSR_STRIDE;
    int deg = g_cursor[node] - beg;
    float4 ald4 = *(const float4*)&g_ald1[node * 4];
    float4 alsS = *(const float4*)&g_als1[node * 4];
    float m0 = lrelu(alsS.x + ald4.x), m1 = lrelu(alsS.y + ald4.y);
    float m2 = lrelu(alsS.z + ald4.z), m3 = lrelu(alsS.w + ald4.w);
    int hl = lane >> 3;

    int idx1 = g_csr[beg + lane];
    float4 a1 = *(const float4*)&g_als1[idx1 * 4];
    bool v1 = lane < deg;
    float p10 = v1 ? __expf(lrelu(a1.x + ald4.x) - m0) : 0.f;
    float p11 = v1 ? __expf(lrelu(a1.y + ald4.y) - m1) : 0.f;
    float p12 = v1 ? __expf(lrelu(a1.z + ald4.z) - m2) : 0.f;
    float p13 = v1 ? __expf(lrelu(a1.w + ald4.w) - m3) : 0.f;
    si[wid][lane] = idx1 * 128;               // prescaled element offset
    *(float4*)&sp[wid][lane][0] = make_float4(p10, p11, p12, p13);
    float dn0 = p10, dn1 = p11, dn2 = p12, dn3 = p13;

    if (deg > 32) {
        int j2 = lane + 32;
        int idx2 = g_csr[beg + j2];
        float4 a2 = *(const float4*)&g_als1[idx2 * 4];
        bool v2 = j2 < deg;
        float p20 = v2 ? __expf(lrelu(a2.x + ald4.x) - m0) : 0.f;
        float p21 = v2 ? __expf(lrelu(a2.y + ald4.y) - m1) : 0.f;
        float p22 = v2 ? __expf(lrelu(a2.z + ald4.z) - m2) : 0.f;
        float p23 = v2 ? __expf(lrelu(a2.w + ald4.w) - m3) : 0.f;
        si[wid][j2] = idx2 * 128;
        *(float4*)&sp[wid][j2][0] = make_float4(p20, p21, p22, p23);
        dn0 += p20; dn1 += p21; dn2 += p22; dn3 += p23;
    }
    __syncwarp();

    float4 acc = make_float4(0.f, 0.f, 0.f, 0.f);
    const __half* hb = h + lane * 4;
    #pragma unroll 8
    for (int t = 0; t < deg; t++) {
        int it = si[wid][t];                  // already element offset
        float pt = sp[wid][t][hl];
        uint2 raw = *(const uint2*)&hb[it];
        float2 f0 = __half22float2(*(__half2*)&raw.x);
        float2 f1 = __half22float2(*(__half2*)&raw.y);
        acc.x += pt * f0.x; acc.y += pt * f0.y;
        acc.z += pt * f1.x; acc.w += pt * f1.y;
    }

    #pragma unroll
    for (int o = 16; o > 0; o >>= 1) {
        dn0 += __shfl_xor_sync(0xffffffffu, dn0, o);
        dn1 += __shfl_xor_sync(0xffffffffu, dn1, o);
        dn2 += __shfl_xor_sync(0xffffffffu, dn2, o);
        dn3 += __shfl_xor_sync(0xffffffffu, dn3, o);
    }
    float dsel = hl == 0 ? dn0 : hl == 1 ? dn1 : hl == 2 ? dn2 : dn3;
    float inv = 1.f / dsel;
    float4 bv = *(const float4*)&b1[lane * 4];
    __align__(8) __half ho[4];
    ho[0] = __float2half_rn(fmaxf(acc.x * inv + bv.x, 0.f));
    ho[1] = __float2half_rn(fmaxf(acc.y * inv + bv.y, 0.f));
    ho[2] = __float2half_rn(fmaxf(acc.z * inv + bv.z, 0.f));
    ho[3] = __float2half_rn(fmaxf(acc.w * inv + bv.w, 0.f));
    *(uint2*)&out[node * 128 + lane * 4] = *(uint2*)ho;
}

// ---------- layer-2 aggregation: fp32 gather, prescaled offsets ----------
__global__ __launch_bounds__(256)
void k_agg2(const float* __restrict__ h, const float* __restrict__ b2,
            float* __restrict__ out) {
    __shared__ float2 sp[8][64];
    int wid = threadIdx.x >> 5, lane = threadIdx.x & 31;
    int node = blockIdx.x * 8 + wid;
    if (node >= N_NODES) return;
    int beg = node * CSR_STRIDE;
    int deg = g_cursor[node] - beg;
    float ald = g_ald2[node];
    float m = lrelu(g_als2[node] + ald);

    int idx1 = g_csr[beg + lane];
    float p1 = (lane < deg) ? __expf(lrelu(g_als2[idx1] + ald) - m) : 0.f;
    sp[wid][lane] = make_float2(p1, __int_as_float(idx1 * 64));   // prescaled
    float dn = p1;
    if (deg > 32) {
        int j2 = lane + 32;
        int idx2 = g_csr[beg + j2];
        float p2 = (j2 < deg) ? __expf(lrelu(g_als2[idx2] + ald) - m) : 0.f;
        sp[wid][j2] = make_float2(p2, __int_as_float(idx2 * 64));
        dn += p2;
    }
    __syncwarp();

    float acc0 = 0.f, acc1 = 0.f;
    const float* hb = h + lane * 2;
    #pragma unroll 8
    for (int t = 0; t < deg; t++) {
        float2 v = sp[wid][t];
        int it = __float_as_int(v.y);
        float2 hv = *(const float2*)&hb[it];
        acc0 += v.x * hv.x;
        acc1 += v.x * hv.y;
    }
    #pragma unroll
    for (int o = 16; o > 0; o >>= 1)
        dn += __shfl_xor_sync(0xffffffffu, dn, o);
    float inv = 1.f / dn;
    float2 o2;
    o2.x = acc0 * inv + b2[lane * 2 + 0];
    o2.y = acc1 * inv + b2[lane * 2 + 1];
    *(float2*)&out[node * 64 + lane * 2] = o2;
}

// ---------------- launch ----------------
extern "C" void kernel_launch(void* const* d_in, const int* in_sizes, int n_in,
                              void* d_out, int out_size) {
    const float* x   = (const float*)d_in[0];
    const int*   ei  = (const int*)d_in[1];
    const float* W1  = (const float*)d_in[2];
    const float* as1 = (const float*)d_in[3];
    const float* ad1 = (const float*)d_in[4];
    const float* b1  = (const float*)d_in[5];
    const float* W2  = (const float*)d_in[6];
    const float* as2 = (const float*)d_in[7];
    const float* ad2 = (const float*)d_in[8];
    const float* b2  = (const float*)d_in[9];
    float* out = (float*)d_out;

    const int* src = ei;
    const int* dst = ei + N_EDGES;

    __half *h1p, *hrp;
    float *h2p, *als1p, *ald1p, *als2p, *ald2p;
    cudaGetSymbolAddress((void**)&h1p, g_h1);
    cudaGetSymbolAddress((void**)&hrp, g_hrelu);
    cudaGetSymbolAddress((void**)&h2p, g_h2);
    cudaGetSymbolAddress((void**)&als1p, g_als1);
    cudaGetSymbolAddress((void**)&ald1p, g_ald1);
    cudaGetSymbolAddress((void**)&als2p, g_als2);
    cudaGetSymbolAddress((void**)&ald2p, g_ald2);

    k_front<<<FRONT_BLOCKS, 256, 49152>>>(x, W1, W2, h1p, as1, ad1,
                                          als1p, ald1p, src, dst);
    k_agg1<<<(N_NODES + 7) / 8, 256>>>(h1p, b1, hrp);
    k_gemm2<<<NTILES1 / 2, 128>>>(hrp, h2p, as2, ad2, als2p, ald2p);
    k_agg2<<<(N_NODES + 7) / 8, 256>>>(h2p, b2, out);
}

// round 17
// speedup vs baseline: 1.0847x; 1.0151x over previous
#include <cuda_runtime.h>
#include <cuda_fp16.h>
#include <cstdint>

#define N_NODES 50000
#define N_EDGES 800000
#define CSR_STRIDE 64          /* max in-degree+1; Poisson(16) -> overflow P ~1e-22 */
#define NEG_SLOPE 0.2f
#define FRONT_BLOCKS 304
#define SCAT_BLOCKS 128
#define NTILES1 782            /* ceil(50000/64) */
#define GEMM_TILES_MAIN 704    /* 176 gemm blocks x 4 tiles; 78-tile tail on scatter blocks */

// ---------------- scratch (static device globals; no runtime alloc) ----------------
__device__ __half g_h1[N_NODES * 128];     // x @ W1 (fp16, gather source)
__device__ __half g_hrelu[N_NODES * 128];  // relu(gat1) (fp16, GEMM2 A)
__device__ float  g_h2[N_NODES * 64];      // hrelu @ W2 (fp32, float4-gather source)
__device__ __half g_W2h[64 * 128];         // W2 fp16, [n][k]
__device__ float  g_als1[N_NODES * 4];
__device__ float  g_ald1[N_NODES * 4];
__device__ float  g_als2[N_NODES];
__device__ float  g_ald2[N_NODES];
__device__ int    g_cursor[N_NODES];
__device__ int    g_csr[N_NODES * CSR_STRIDE];
__device__ int    g_bar;                   // epoch barrier among scatter blocks

__device__ __forceinline__ float lrelu(float e) {
    return e >= 0.f ? e : NEG_SLOPE * e;
}

__device__ __forceinline__ uint32_t smem_u32(const void* p) {
    return (uint32_t)__cvta_generic_to_shared(p);
}

__device__ __forceinline__ void ldsm4(uint32_t& r0, uint32_t& r1, uint32_t& r2,
                                      uint32_t& r3, uint32_t addr) {
    asm volatile("ldmatrix.sync.aligned.m8n8.x4.shared.b16 {%0,%1,%2,%3}, [%4];"
                 : "=r"(r0), "=r"(r1), "=r"(r2), "=r"(r3) : "r"(addr));
}

__device__ __forceinline__ void mma16816(float* d, const uint32_t* a, const uint32_t* b) {
    asm volatile(
        "mma.sync.aligned.m16n8k16.row.col.f32.f16.f16.f32 "
        "{%0,%1,%2,%3}, {%4,%5,%6,%7}, {%8,%9}, {%0,%1,%2,%3};"
        : "+f"(d[0]), "+f"(d[1]), "+f"(d[2]), "+f"(d[3])
        : "r"(a[0]), "r"(a[1]), "r"(a[2]), "r"(a[3]), "r"(b[0]), "r"(b[1]));
}

__device__ __forceinline__ void cp16(uint32_t dst, const void* src) {
    asm volatile("cp.async.cg.shared.global [%0], [%1], 16;" :: "r"(dst), "l"(src));
}

// ---- fused front: cursor/W2h init + barrier + scatter (blocks 0..127),
//      HMMA GEMM1 + fused logits1 (all blocks; W1 converted inline) ----
__global__ __launch_bounds__(256)
void k_front(const float* __restrict__ A,
             const float* __restrict__ W1, const float* __restrict__ W2,
             __half* __restrict__ C,
             const float* __restrict__ a_s, const float* __restrict__ a_d,
             float* __restrict__ als, float* __restrict__ ald,
             const int* __restrict__ src, const int* __restrict__ dst) {
    extern __shared__ uint4 sm[];        // [0,1024): A 64x16; [1024,3072): W 128x16
    uint4* Asw = sm;
    uint4* Wsw = sm + 1024;

    int tid = threadIdx.x;
    int bid = blockIdx.x;

    int t0, t1;
    if (bid < SCAT_BLOCKS) {
        // ---- phase 0: init cursors + self-loops + W2h ----
        for (int i = bid * 256 + tid; i < N_NODES; i += SCAT_BLOCKS * 256) {
            g_csr[i * CSR_STRIDE] = i;          // appended self-loop in slot 0
            g_cursor[i] = i * CSR_STRIDE + 1;
        }
        {
            int u = bid * 256 + tid;
            if (u < 64 * 128) {
                int k = u >> 6, n = u & 63;
                g_W2h[n * 128 + k] = __float2half_rn(W2[k * 64 + n]);
            }
        }
        __syncthreads();
        // ---- epoch barrier among the 128 scatter blocks (all wave-1 resident) ----
        if (tid == 0) {
            __threadfence();
            int v = atomicAdd(&g_bar, 1) + 1;
            int target = ((v - 1) / SCAT_BLOCKS + 1) * SCAT_BLOCKS;
            while (atomicAdd(&g_bar, 0) < target) { }
        }
        __syncthreads();

        // ---- phase 1: scatter, 4-way unrolled ----
        constexpr int STRIDE = SCAT_BLOCKS * 256;     // 32768
        int e = bid * 256 + tid;
        for (; e + 3 * STRIDE < N_EDGES; e += 4 * STRIDE) {
            int s0 = src[e],              d0 = dst[e];
            int s1 = src[e + STRIDE],     d1 = dst[e + STRIDE];
            int s2 = src[e + 2 * STRIDE], d2 = dst[e + 2 * STRIDE];
            int s3 = src[e + 3 * STRIDE], d3 = dst[e + 3 * STRIDE];
            int p0 = (s0 != d0) ? atomicAdd(&g_cursor[d0], 1) : -1;
            int p1 = (s1 != d1) ? atomicAdd(&g_cursor[d1], 1) : -1;
            int p2 = (s2 != d2) ? atomicAdd(&g_cursor[d2], 1) : -1;
            int p3 = (s3 != d3) ? atomicAdd(&g_cursor[d3], 1) : -1;
            if (p0 >= 0) g_csr[p0] = s0;
            if (p1 >= 0) g_csr[p1] = s1;
            if (p2 >= 0) g_csr[p2] = s2;
            if (p3 >= 0) g_csr[p3] = s3;
        }
        for (; e < N_EDGES; e += STRIDE) {
            int s = src[e], d = dst[e];
            if (s != d) {
                int p = atomicAdd(&g_cursor[d], 1);
                g_csr[p] = s;
            }
        }
        t0 = GEMM_TILES_MAIN + bid;
        t1 = (bid < NTILES1 - GEMM_TILES_MAIN) ? t0 + 1 : t0;
    } else {
        int nb = bid - SCAT_BLOCKS;
        t0 = nb * 4; t1 = t0 + 4;
    }
    if (t0 >= t1) return;

    // W1 fp32 -> fp16 swizzled smem (inline conversion; W1 is L2-resident)
    for (int u = tid; u < 2048; u += 256) {
        int kc = u >> 7, n = u & 127;
        __align__(16) __half tmp[8];
        #pragma unroll
        for (int i = 0; i < 8; i++)
            tmp[i] = __float2half_rn(W1[(kc * 8 + i) * 128 + n]);
        Wsw[n * 16 + (kc ^ (n & 7))] = *(const uint4*)tmp;
    }

    int lane = tid & 31, wid = tid >> 5;
    int wm = wid >> 2, wn = wid & 3;
    int grp = lane >> 2, qid = lane & 3;

    float asr[4][2], adr[4][2];
    #pragma unroll
    for (int nj = 0; nj < 4; nj++) {
        int col = wn * 32 + nj * 8 + qid * 2;
        asr[nj][0] = a_s[col]; asr[nj][1] = a_s[col + 1];
        adr[nj][0] = a_d[col]; adr[nj][1] = a_d[col + 1];
    }

    uint32_t aBase = smem_u32(Asw);
    uint32_t wBase = smem_u32(Wsw);
    int aRowL = (lane & 7) + ((lane >> 3) & 1) * 8;
    int aChkL = lane >> 4;
    int bRowL = (lane & 7) + (lane >> 4) * 8;
    int bChkL = (lane >> 3) & 1;

    for (int tile = t0; tile < t1; tile++) {
        int rowBase = tile * 64;
        __syncthreads();
        for (int u = tid; u < 1024; u += 256) {
            int r = u >> 4, c = u & 15;
            int row = rowBase + r;
            uint4 val = make_uint4(0u, 0u, 0u, 0u);
            if (row < N_NODES) {
                float4 f0 = *(const float4*)&A[row * 128 + c * 8];
                float4 f1 = *(const float4*)&A[row * 128 + c * 8 + 4];
                __align__(16) __half h8[8];
                h8[0] = __float2half_rn(f0.x); h8[1] = __float2half_rn(f0.y);
                h8[2] = __float2half_rn(f0.z); h8[3] = __float2half_rn(f0.w);
                h8[4] = __float2half_rn(f1.x); h8[5] = __float2half_rn(f1.y);
                h8[6] = __float2half_rn(f1.z); h8[7] = __float2half_rn(f1.w);
                val = *(const uint4*)h8;
            }
            Asw[r * 16 + (c ^ (r & 7))] = val;
        }
        __syncthreads();

        float acc[2][4][4];
        #pragma unroll
        for (int mi = 0; mi < 2; mi++)
            #pragma unroll
            for (int nj = 0; nj < 4; nj++)
                #pragma unroll
                for (int q = 0; q < 4; q++) acc[mi][nj][q] = 0.f;

        #pragma unroll
        for (int ks = 0; ks < 8; ks++) {
            uint32_t aF[2][4], bF[2][4];
            #pragma unroll
            for (int mi = 0; mi < 2; mi++) {
                int row = wm * 32 + mi * 16 + aRowL;
                int ch = ks * 2 + aChkL;
                ldsm4(aF[mi][0], aF[mi][1], aF[mi][2], aF[mi][3],
                      aBase + (uint32_t)(row * 16 + (ch ^ (row & 7))) * 16u);
            }
            #pragma unroll
            for (int pr = 0; pr < 2; pr++) {
                int n = wn * 32 + pr * 16 + bRowL;
                int ch = ks * 2 + bChkL;
                ldsm4(bF[pr][0], bF[pr][1], bF[pr][2], bF[pr][3],
                      wBase + (uint32_t)(n * 16 + (ch ^ (n & 7))) * 16u);
            }
            #pragma unroll
            for (int mi = 0; mi < 2; mi++)
                #pragma unroll
                for (int nj = 0; nj < 4; nj++)
                    mma16816(acc[mi][nj], aF[mi], &bF[nj >> 1][(nj & 1) * 2]);
        }

        #pragma unroll
        for (int mi = 0; mi < 2; mi++) {
            int rLo = rowBase + wm * 32 + mi * 16 + grp;
            int rHi = rLo + 8;
            float psLo = 0.f, pdLo = 0.f, psHi = 0.f, pdHi = 0.f;
            #pragma unroll
            for (int nj = 0; nj < 4; nj++) {
                psLo += acc[mi][nj][0] * asr[nj][0] + acc[mi][nj][1] * asr[nj][1];
                pdLo += acc[mi][nj][0] * adr[nj][0] + acc[mi][nj][1] * adr[nj][1];
                psHi += acc[mi][nj][2] * asr[nj][0] + acc[mi][nj][3] * asr[nj][1];
                pdHi += acc[mi][nj][2] * adr[nj][0] + acc[mi][nj][3] * adr[nj][1];
                int col = wn * 32 + nj * 8 + qid * 2;
                if (rLo < N_NODES)
                    *(__half2*)&C[rLo * 128 + col] =
                        __floats2half2_rn(acc[mi][nj][0], acc[mi][nj][1]);
                if (rHi < N_NODES)
                    *(__half2*)&C[rHi * 128 + col] =
                        __floats2half2_rn(acc[mi][nj][2], acc[mi][nj][3]);
            }
            psLo += __shfl_xor_sync(~0u, psLo, 1); psLo += __shfl_xor_sync(~0u, psLo, 2);
            pdLo += __shfl_xor_sync(~0u, pdLo, 1); pdLo += __shfl_xor_sync(~0u, pdLo, 2);
            psHi += __shfl_xor_sync(~0u, psHi, 1); psHi += __shfl_xor_sync(~0u, psHi, 2);
            pdHi += __shfl_xor_sync(~0u, pdHi, 1); pdHi += __shfl_xor_sync(~0u, pdHi, 2);
            if (qid == 0) {
                if (rLo < N_NODES) { als[rLo * 4 + wn] = psLo; ald[rLo * 4 + wn] = pdLo; }
                if (rHi < N_NODES) { als[rHi * 4 + wn] = psHi; ald[rHi * 4 + wn] = pdHi; }
            }
        }
    }
}

// ---- GEMM2 (HMMA): 2 tiles per block, double-buffered A, fp32 output ----
__global__ __launch_bounds__(128)
void k_gemm2(const __half* __restrict__ Ah,
             float* __restrict__ C,
             const float* __restrict__ a_s, const float* __restrict__ a_d,
             float* __restrict__ als, float* __restrict__ ald) {
    __shared__ uint4 Wsw[1024];      // 16KB
    __shared__ uint4 Asw[2][1024];   // 2 x 16KB

    int tid = threadIdx.x;
    int tileBase = blockIdx.x * 2;

    #pragma unroll
    for (int r = 0; r < 8; r++) {
        int u = tid + r * 128;
        int n = u >> 4, kc = u & 15;
        cp16(smem_u32(&Wsw[n * 16 + (kc ^ (n & 7))]), &g_W2h[n * 128 + kc * 8]);
    }
    asm volatile("cp.async.commit_group;");

    #pragma unroll
    for (int r = 0; r < 8; r++) {
        int u = tid + r * 128;
        int rr = u >> 4, c = u & 15;
        int row = tileBase * 64 + rr;
        if (row < N_NODES)
            cp16(smem_u32(&Asw[0][rr * 16 + (c ^ (rr & 7))]), &Ah[row * 128 + c * 8]);
        else
            Asw[0][rr * 16 + (c ^ (rr & 7))] = make_uint4(0u, 0u, 0u, 0u);
    }
    asm volatile("cp.async.commit_group;");

    int lane = tid & 31, wid = tid >> 5;
    int grp = lane >> 2, qid = lane & 3;
    uint32_t wBase = smem_u32(Wsw);
    int aRowL = (lane & 7) + ((lane >> 3) & 1) * 8;
    int aChkL = lane >> 4;
    int bRowL = (lane & 7) + (lane >> 4) * 8;
    int bChkL = (lane >> 3) & 1;

    float asr[8][2], adr[8][2];
    #pragma unroll
    for (int nj = 0; nj < 8; nj++) {
        int col = nj * 8 + qid * 2;
        asr[nj][0] = a_s[col]; asr[nj][1] = a_s[col + 1];
        adr[nj][0] = a_d[col]; adr[nj][1] = a_d[col + 1];
    }

    #pragma unroll
    for (int tt = 0; tt < 2; tt++) {
        int tile = tileBase + tt;
        int rowBase = tile * 64;

        if (tt == 0) {
            #pragma unroll
            for (int r = 0; r < 8; r++) {
                int u = tid + r * 128;
                int rr = u >> 4, c = u & 15;
                int row = (tileBase + 1) * 64 + rr;
                if (row < N_NODES)
                    cp16(smem_u32(&Asw[1][rr * 16 + (c ^ (rr & 7))]),
                         &Ah[row * 128 + c * 8]);
                else
                    Asw[1][rr * 16 + (c ^ (rr & 7))] = make_uint4(0u, 0u, 0u, 0u);
            }
            asm volatile("cp.async.commit_group;");
            asm volatile("cp.async.wait_group 1;");   // W + A0 done
        } else {
            asm volatile("cp.async.wait_group 0;");   // A1 done
        }
        __syncthreads();

        uint32_t aBase = smem_u32(Asw[tt]);
        float acc[8][4];
        #pragma unroll
        for (int nj = 0; nj < 8; nj++)
            #pragma unroll
            for (int q = 0; q < 4; q++) acc[nj][q] = 0.f;

        #pragma unroll
        for (int ks = 0; ks < 8; ks++) {
            uint32_t aF[4], bF[4][4];
            {
                int row = wid * 16 + aRowL;
                int ch = ks * 2 + aChkL;
                ldsm4(aF[0], aF[1], aF[2], aF[3],
                      aBase + (uint32_t)(row * 16 + (ch ^ (row & 7))) * 16u);
            }
            #pragma unroll
            for (int pr = 0; pr < 4; pr++) {
                int n = pr * 16 + bRowL;
                int ch = ks * 2 + bChkL;
                ldsm4(bF[pr][0], bF[pr][1], bF[pr][2], bF[pr][3],
                      wBase + (uint32_t)(n * 16 + (ch ^ (n & 7))) * 16u);
            }
            #pragma unroll
            for (int nj = 0; nj < 8; nj++)
                mma16816(acc[nj], aF, &bF[nj >> 1][(nj & 1) * 2]);
        }

        int rLo = rowBase + wid * 16 + grp;
        int rHi = rLo + 8;
        float psLo = 0.f, pdLo = 0.f, psHi = 0.f, pdHi = 0.f;
        #pragma unroll
        for (int nj = 0; nj < 8; nj++) {
            psLo += acc[nj][0] * asr[nj][0] + acc[nj][1] * asr[nj][1];
            pdLo += acc[nj][0] * adr[nj][0] + acc[nj][1] * adr[nj][1];
            psHi += acc[nj][2] * asr[nj][0] + acc[nj][3] * asr[nj][1];
            pdHi += acc[nj][2] * adr[nj][0] + acc[nj][3] * adr[nj][1];
            int col = nj * 8 + qid * 2;
            if (rLo < N_NODES)
                *(float2*)&C[rLo * 64 + col] = make_float2(acc[nj][0], acc[nj][1]);
            if (rHi < N_NODES)
                *(float2*)&C[rHi * 64 + col] = make_float2(acc[nj][2], acc[nj][3]);
        }
        psLo += __shfl_xor_sync(~0u, psLo, 1); psLo += __shfl_xor_sync(~0u, psLo, 2);
        pdLo += __shfl_xor_sync(~0u, pdLo, 1); pdLo += __shfl_xor_sync(~0u, pdLo, 2);
        psHi += __shfl_xor_sync(~0u, psHi, 1); psHi += __shfl_xor_sync(~0u, psHi, 2);
        pdHi += __shfl_xor_sync(~0u, pdHi, 1); pdHi += __shfl_xor_sync(~0u, pdHi, 2);
        if (qid == 0) {
            if (rLo < N_NODES) { als[rLo] = psLo; ald[rLo] = pdLo; }
            if (rHi < N_NODES) { als[rHi] = psHi; ald[rHi] = pdHi; }
        }
    }
}

// ---------- layer-1 aggregation: flat 2-chunk, smem-staged (p, prescaled idx) ------
__global__ __launch_bounds__(256)
void k_agg1(const __half* __restrict__ h, const float* __restrict__ b1,
            __half* __restrict__ out) {
    __shared__ float sp[8][64][4];
    __shared__ int   si[8][64];
    int wid = threadIdx.x >> 5, lane = threadIdx.x & 31;
    int node = blockIdx.x * 8 + wid;
    if (node >= N_NODES) return;
    int beg = node * CSR_STRIDE;
    int deg = g_cursor[node] - beg;
    float4 ald4 = *(const float4*)&g_ald1[node * 4];
    float4 alsS = *(const float4*)&g_als1[node * 4];
    float m0 = lrelu(alsS.x + ald4.x), m1 = lrelu(alsS.y + ald4.y);
    float m2 = lrelu(alsS.z + ald4.z), m3 = lrelu(alsS.w + ald4.w);
    int hl = lane >> 3;

    int idx1 = g_csr[beg + lane];
    float4 a1 = *(const float4*)&g_als1[idx1 * 4];
    bool v1 = lane < deg;
    float p10 = v1 ? __expf(lrelu(a1.x + ald4.x) - m0) : 0.f;
    float p11 = v1 ? __expf(lrelu(a1.y + ald4.y) - m1) : 0.f;
    float p12 = v1 ? __expf(lrelu(a1.z + ald4.z) - m2) : 0.f;
    float p13 = v1 ? __expf(lrelu(a1.w + ald4.w) - m3) : 0.f;
    si[wid][lane] = idx1 * 128;
    *(float4*)&sp[wid][lane][0] = make_float4(p10, p11, p12, p13);
    float dn0 = p10, dn1 = p11, dn2 = p12, dn3 = p13;

    if (deg > 32) {
        int j2 = lane + 32;
        int idx2 = g_csr[beg + j2];
        float4 a2 = *(const float4*)&g_als1[idx2 * 4];
        bool v2 = j2 < deg;
        float p20 = v2 ? __expf(lrelu(a2.x + ald4.x) - m0) : 0.f;
        float p21 = v2 ? __expf(lrelu(a2.y + ald4.y) - m1) : 0.f;
        float p22 = v2 ? __expf(lrelu(a2.z + ald4.z) - m2) : 0.f;
        float p23 = v2 ? __expf(lrelu(a2.w + ald4.w) - m3) : 0.f;
        si[wid][j2] = idx2 * 128;
        *(float4*)&sp[wid][j2][0] = make_float4(p20, p21, p22, p23);
        dn0 += p20; dn1 += p21; dn2 += p22; dn3 += p23;
    }
    __syncwarp();

    float4 acc = make_float4(0.f, 0.f, 0.f, 0.f);
    const __half* hb = h + lane * 4;
    #pragma unroll 8
    for (int t = 0; t < deg; t++) {
        int it = si[wid][t];
        float pt = sp[wid][t][hl];
        uint2 raw = *(const uint2*)&hb[it];
        float2 f0 = __half22float2(*(__half2*)&raw.x);
        float2 f1 = __half22float2(*(__half2*)&raw.y);
        acc.x += pt * f0.x; acc.y += pt * f0.y;
        acc.z += pt * f1.x; acc.w += pt * f1.y;
    }

    #pragma unroll
    for (int o = 16; o > 0; o >>= 1) {
        dn0 += __shfl_xor_sync(0xffffffffu, dn0, o);
        dn1 += __shfl_xor_sync(0xffffffffu, dn1, o);
        dn2 += __shfl_xor_sync(0xffffffffu, dn2, o);
        dn3 += __shfl_xor_sync(0xffffffffu, dn3, o);
    }
    float dsel = hl == 0 ? dn0 : hl == 1 ? dn1 : hl == 2 ? dn2 : dn3;
    float inv = 1.f / dsel;
    float4 bv = *(const float4*)&b1[lane * 4];
    __align__(8) __half ho[4];
    ho[0] = __float2half_rn(fmaxf(acc.x * inv + bv.x, 0.f));
    ho[1] = __float2half_rn(fmaxf(acc.y * inv + bv.y, 0.f));
    ho[2] = __float2half_rn(fmaxf(acc.z * inv + bv.z, 0.f));
    ho[3] = __float2half_rn(fmaxf(acc.w * inv + bv.w, 0.f));
    *(uint2*)&out[node * 128 + lane * 4] = *(uint2*)ho;
}

// ---- layer-2 aggregation: TWO edges per warp-iteration, float4 lanes ----
// lanes 0-15 process edge t, lanes 16-31 edge t+1; each lane covers 4 features.
// Odd-deg safe: slot `deg` is always staged with p=0.
__global__ __launch_bounds__(256)
void k_agg2(const float* __restrict__ h, const float* __restrict__ b2,
            float* __restrict__ out) {
    __shared__ float2 sp[8][64];
    int wid = threadIdx.x >> 5, lane = threadIdx.x & 31;
    int node = blockIdx.x * 8 + wid;
    if (node >= N_NODES) return;
    int beg = node * CSR_STRIDE;
    int deg = g_cursor[node] - beg;
    float ald = g_ald2[node];
    float m = lrelu(g_als2[node] + ald);

    int idx1 = g_csr[beg + lane];
    float p1 = (lane < deg) ? __expf(lrelu(g_als2[idx1] + ald) - m) : 0.f;
    sp[wid][lane] = make_float2(p1, __int_as_float(idx1 * 64));
    float dn = p1;
    if (deg > 32) {
        int j2 = lane + 32;
        int idx2 = g_csr[beg + j2];
        float p2 = (j2 < deg) ? __expf(lrelu(g_als2[idx2] + ald) - m) : 0.f;
        sp[wid][j2] = make_float2(p2, __int_as_float(idx2 * 64));
        dn += p2;
    }
    __syncwarp();

    int half = lane >> 4;              // 0: edge t, 1: edge t+1
    int fl = (lane & 15) * 4;          // feature base
    const float* hb = h + fl;
    float4 acc = make_float4(0.f, 0.f, 0.f, 0.f);
    #pragma unroll 4
    for (int t = 0; t < deg; t += 2) {
        float2 v = sp[wid][t + half];
        int off = __float_as_int(v.y);
        float4 hv = *(const float4*)&hb[off];
        acc.x += v.x * hv.x; acc.y += v.x * hv.y;
        acc.z += v.x * hv.z; acc.w += v.x * hv.w;
    }
    // combine the two edge-halves (features identical across halves)
    acc.x += __shfl_xor_sync(0xffffffffu, acc.x, 16);
    acc.y += __shfl_xor_sync(0xffffffffu, acc.y, 16);
    acc.z += __shfl_xor_sync(0xffffffffu, acc.z, 16);
    acc.w += __shfl_xor_sync(0xffffffffu, acc.w, 16);

    #pragma unroll
    for (int o = 16; o > 0; o >>= 1)
        dn += __shfl_xor_sync(0xffffffffu, dn, o);
    float inv = 1.f / dn;
    if (half == 0) {
        float4 bv = *(const float4*)&b2[fl];
        float4 o4;
        o4.x = acc.x * inv + bv.x;
        o4.y = acc.y * inv + bv.y;
        o4.z = acc.z * inv + bv.z;
        o4.w = acc.w * inv + bv.w;
        *(float4*)&out[node * 64 + fl] = o4;
    }
}

// ---------------- launch ----------------
extern "C" void kernel_launch(void* const* d_in, const int* in_sizes, int n_in,
                              void* d_out, int out_size) {
    const float* x   = (const float*)d_in[0];
    const int*   ei  = (const int*)d_in[1];
    const float* W1  = (const float*)d_in[2];
    const float* as1 = (const float*)d_in[3];
    const float* ad1 = (const float*)d_in[4];
    const float* b1  = (const float*)d_in[5];
    const float* W2  = (const float*)d_in[6];
    const float* as2 = (const float*)d_in[7];
    const float* ad2 = (const float*)d_in[8];
    const float* b2  = (const float*)d_in[9];
    float* out = (float*)d_out;

    const int* src = ei;
    const int* dst = ei + N_EDGES;

    __half *h1p, *hrp;
    float *h2p, *als1p, *ald1p, *als2p, *ald2p;
    cudaGetSymbolAddress((void**)&h1p, g_h1);
    cudaGetSymbolAddress((void**)&hrp, g_hrelu);
    cudaGetSymbolAddress((void**)&h2p, g_h2);
    cudaGetSymbolAddress((void**)&als1p, g_als1);
    cudaGetSymbolAddress((void**)&ald1p, g_ald1);
    cudaGetSymbolAddress((void**)&als2p, g_als2);
    cudaGetSymbolAddress((void**)&ald2p, g_ald2);

    k_front<<<FRONT_BLOCKS, 256, 49152>>>(x, W1, W2, h1p, as1, ad1,
                                          als1p, ald1p, src, dst);
    k_agg1<<<(N_NODES + 7) / 8, 256>>>(h1p, b1, hrp);
    k_gemm2<<<NTILES1 / 2, 128>>>(hrp, h2p, as2, ad2, als2p, ald2p);
    k_agg2<<<(N_NODES + 7) / 8, 256>>>(h2p, b2, out);
}